// round 11
// baseline (speedup 1.0000x reference)
#include <cuda_runtime.h>
#include <math.h>
#include <stdint.h>

#define cB 4
#define cL 512
#define cD 512
#define cH 16
#define cKH 32
#define cFF 2048
#define cNL 8
#define cND 14
#define cM 512
#define cBL (cB*cL)
#define SCALEF 0.17677669529663687f  // 1/sqrt(32)

// ------------------------- scratch (static device globals) ------------------
__device__ float g_h [cBL*cD];
__device__ float g_q [cBL*cD];
__device__ float g_k [cBL*cD];
__device__ float g_v [cBL*cD];
__device__ float g_z [cBL*cD];
__device__ float g_o [cBL*cD];
__device__ float g_o2[cBL*cD];
__device__ float g_h2[cBL*cD];
__device__ float g_f [cBL*cFF];
__device__ float g_qE [cB*cH*cL*cND];
__device__ float g_kE [cB*cH*cL*cND];
__device__ unsigned char g_didx[cB*cL*cL];
__device__ float g_Vsum[cND*cKH];
__device__ float g_sumKkr[cND];
__device__ float g_zb[cD];          // zero bias (never written)

// packed bf16 hi/lo weights per layer (u32 offsets):
//   wq @0, wk @262144, wv @524288, wo @786432, w1 @1048576, w2 @2097152
#define WPL 3145728
__device__ uint32_t g_wp[(size_t)cNL * WPL];

// ------------------------- helpers ------------------------------------------
__device__ __forceinline__ uint32_t smem_u32(const void* p) {
    uint32_t a;
    asm("{ .reg .u64 t; cvta.to.shared.u64 t, %1; cvt.u32.u64 %0, t; }" : "=r"(a) : "l"(p));
    return a;
}
__device__ __forceinline__ void cpasync16(uint32_t dst, const void* src) {
    asm volatile("cp.async.cg.shared.global [%0], [%1], 16;" :: "r"(dst), "l"(src));
}
#define CP_COMMIT() asm volatile("cp.async.commit_group;" ::: "memory")
#define CP_WAIT1()  asm volatile("cp.async.wait_group 1;" ::: "memory")

// split (x0,x1) into packed bf16x2 hi + lo, low half = x0
__device__ __forceinline__ void split2(float x0, float x1, uint32_t& hi, uint32_t& lo) {
    uint32_t h;
    asm("cvt.rn.bf16x2.f32 %0, %1, %2;" : "=r"(h) : "f"(x1), "f"(x0));
    float h0 = __uint_as_float(h << 16);
    float h1 = __uint_as_float(h & 0xffff0000u);
    uint32_t l;
    asm("cvt.rn.bf16x2.f32 %0, %1, %2;" : "=r"(l) : "f"(x1 - h1), "f"(x0 - h0));
    hi = h; lo = l;
}
__device__ __forceinline__ void mma_bf16(float* c, const uint32_t* a, const uint32_t* b) {
    asm volatile(
        "mma.sync.aligned.m16n8k16.row.col.f32.bf16.bf16.f32 "
        "{%0,%1,%2,%3}, {%4,%5,%6,%7}, {%8,%9}, {%0,%1,%2,%3};\n"
        : "+f"(c[0]), "+f"(c[1]), "+f"(c[2]), "+f"(c[3])
        : "r"(a[0]), "r"(a[1]), "r"(a[2]), "r"(a[3]), "r"(b[0]), "r"(b[1]));
}

// ------------------------- weight conversion pre-pass ------------------------
__global__ void wconv_kernel(const float* __restrict__ src, uint32_t* __restrict__ dst,
                             int K, int N, size_t sStride, size_t dStride) {
    int ly = blockIdx.z;
    const float* s = src + (size_t)ly * sStride;
    uint32_t* d = dst + (size_t)ly * dStride;
    int t = threadIdx.x;
    int n  = blockIdx.x * 32 + (t & 31);
    int k2 = blockIdx.y * 8 + (t >> 5);
    float w0 = s[(size_t)(2 * k2) * N + n];
    float w1 = s[(size_t)(2 * k2 + 1) * N + n];
    uint32_t hi, lo;
    split2(w0, w1, hi, lo);
    size_t loSz = (size_t)(K / 2) * N;
    d[(size_t)k2 * N + n] = hi;
    d[loSz + (size_t)k2 * N + n] = lo;
}

// ------------------------- bf16 3-term tensor-core GEMM ---------------------
// BM=64, warps 2(M)x4(N). B pre-packed bf16 hi/lo.
struct GArgs {
    const float* A;
    const uint32_t* W0; const uint32_t* W1; const uint32_t* W2;
    const float* c0; const float* c1; const float* c2;
    float* C0; float* C1; float* C2;
};

#define A_STRIDE 20
#define A_FLOATS (64 * A_STRIDE)

template<int BN, bool GELU, bool TRIPLE>
__global__ __launch_bounds__(256, 3) void mma_gemm(GArgs args, int Md, int Nd, int Kd,
                                                   int ldA, int aStep, int loOff) {
    constexpr int BSTR = BN + 8;                    // u32 stride
    constexpr int STAGE = A_FLOATS + 16 * BSTR;     // floats per stage
    constexpr int NT = BN / 32;                     // n-tiles per warp (4 or 2)
    constexpr int BCH = 8 * BN / 4;                 // float4 chunks per hi array
    extern __shared__ float smem[];
    uint32_t smb = smem_u32(smem);

    int t = threadIdx.x;
    const float* A = args.A;
    const uint32_t* W; const float* bias; float* C;
    if (TRIPLE) {
        int z = blockIdx.z;
        A   += (size_t)z * aStep;
        W    = (z == 0) ? args.W0 : (z == 1) ? args.W1 : args.W2;
        bias = (z == 0) ? args.c0 : (z == 1) ? args.c1 : args.c2;
        C    = (z == 0) ? args.C0 : (z == 1) ? args.C1 : args.C2;
    } else { W = args.W0; bias = args.c0; C = args.C0; }

    int m0 = blockIdx.y * 64, n0 = blockIdx.x * BN;

    auto issue = [&](int ch, int s) {
        int k0  = ch << 4;
        int k2b = ch << 3;
        uint32_t sa = smb + (uint32_t)(s * STAGE) * 4;
        uint32_t sb = sa + A_FLOATS * 4;
        {
            int row = t >> 2, c4 = (t & 3) << 2;    // 64 rows x 16 k
            cpasync16(sa + (uint32_t)(row * A_STRIDE + c4) * 4,
                      &A[(size_t)(m0 + row) * ldA + k0 + c4]);
        }
#pragma unroll
        for (int it = 0; it < (2 * BCH) / 256; it++) {
            int idx = t + it * 256;
            int arr = (idx >= BCH) ? 1 : 0;
            int ci  = idx - arr * BCH;
            int row = ci / (BN / 4), c4 = (ci % (BN / 4)) << 2;
            cpasync16(sb + (uint32_t)((arr * 8 + row) * BSTR + c4) * 4,
                      &W[(size_t)(arr ? loOff : 0) + (size_t)(k2b + row) * Nd + n0 + c4]);
        }
    };

    int lane = t & 31, wid = t >> 5;
    int wm = wid & 1, wn = wid >> 1;    // 2 x 4
    int gr = lane >> 2, t4 = lane & 3;

    float c[2][NT][4];
#pragma unroll
    for (int i = 0; i < 2; i++)
#pragma unroll
        for (int j = 0; j < NT; j++)
#pragma unroll
            for (int q = 0; q < 4; q++) c[i][j][q] = 0.f;

    int nc = Kd >> 4;
    issue(0, 0); CP_COMMIT();
    issue(1, 1); CP_COMMIT();

    for (int ch = 0; ch < nc; ch++) {
        CP_WAIT1();
        __syncthreads();
        if (ch + 2 < nc) issue(ch + 2, (ch + 2) % 3);
        CP_COMMIT();

        const float* sA = smem + (ch % 3) * STAGE;
        const uint32_t* sBhi = (const uint32_t*)(sA + A_FLOATS);
        const uint32_t* sBlo = sBhi + 8 * BSTR;

        uint32_t ah[2][4], al[2][4];
#pragma unroll
        for (int i = 0; i < 2; i++) {
            int r0 = wm * 32 + i * 16 + gr;
            float2 p00 = *(const float2*)&sA[r0 * A_STRIDE + 2 * t4];
            float2 p10 = *(const float2*)&sA[(r0 + 8) * A_STRIDE + 2 * t4];
            float2 p01 = *(const float2*)&sA[r0 * A_STRIDE + 2 * t4 + 8];
            float2 p11 = *(const float2*)&sA[(r0 + 8) * A_STRIDE + 2 * t4 + 8];
            split2(p00.x, p00.y, ah[i][0], al[i][0]);
            split2(p10.x, p10.y, ah[i][1], al[i][1]);
            split2(p01.x, p01.y, ah[i][2], al[i][2]);
            split2(p11.x, p11.y, ah[i][3], al[i][3]);
        }
#pragma unroll
        for (int j = 0; j < NT; j++) {
            int n = wn * (BN / 4) + j * 8 + gr;
            uint32_t bh[2], bl[2];
            bh[0] = sBhi[t4 * BSTR + n];
            bh[1] = sBhi[(t4 + 4) * BSTR + n];
            bl[0] = sBlo[t4 * BSTR + n];
            bl[1] = sBlo[(t4 + 4) * BSTR + n];
#pragma unroll
            for (int i = 0; i < 2; i++) {
                mma_bf16(c[i][j], al[i], bh);
                mma_bf16(c[i][j], ah[i], bl);
                mma_bf16(c[i][j], ah[i], bh);
            }
        }
    }

#pragma unroll
    for (int i = 0; i < 2; i++) {
        int rb = m0 + wm * 32 + i * 16 + gr;
#pragma unroll
        for (int j = 0; j < NT; j++) {
            int col = n0 + wn * (BN / 4) + j * 8 + t4 * 2;
            float2 bb = *(const float2*)&bias[col];
            float v0 = c[i][j][0] + bb.x, v1 = c[i][j][1] + bb.y;
            float v2 = c[i][j][2] + bb.x, v3 = c[i][j][3] + bb.y;
            if (GELU) {
                v0 = 0.5f * v0 * (1.0f + erff(v0 * 0.70710678118654752f));
                v1 = 0.5f * v1 * (1.0f + erff(v1 * 0.70710678118654752f));
                v2 = 0.5f * v2 * (1.0f + erff(v2 * 0.70710678118654752f));
                v3 = 0.5f * v3 * (1.0f + erff(v3 * 0.70710678118654752f));
            }
            *(float2*)&C[(size_t)rb * Nd + col] = make_float2(v0, v1);
            *(float2*)&C[(size_t)(rb + 8) * Nd + col] = make_float2(v2, v3);
        }
    }
}

// ------------------------- distance bucketize -------------------------------
__global__ void didx_kernel(const float* __restrict__ dist) {
    int i = blockIdx.x * blockDim.x + threadIdx.x;
    float d = dist[i];
    int idx = 0;
#pragma unroll
    for (int j = 1; j <= 14; j++) idx += (10.0f * (float)j < d) ? 1 : 0;
    if (idx > 13) idx = 13;
    g_didx[i] = (unsigned char)idx;
}

// ------------------------- embedding gather ---------------------------------
__global__ void embed_kernel(const int* __restrict__ ct, const float* __restrict__ emb) {
    int row = blockIdx.x;
    int c0  = ct[row];
    for (int c = threadIdx.x; c < cD; c += blockDim.x)
        g_h[(size_t)row * cD + c] = emb[(size_t)c0 * cD + c];
}

// ------------------------- tiny precompute ----------------------------------
__global__ void prep_kernel(const float* __restrict__ Kkr,
                            const float* __restrict__ Vqk,
                            const float* __restrict__ Vqr,
                            const float* __restrict__ Vkr) {
    int t = threadIdx.x;
    if (t < cND * cKH) g_Vsum[t] = Vqk[t] + Vqr[t] + Vkr[t];
    if (t < cND) {
        float s = 0.f;
        for (int k = 0; k < cKH; k++) s += Kkr[t * cKH + k];
        g_sumKkr[t] = s;
    }
}

// ------------------------- qE / kE ------------------------------------------
__global__ void qke_kernel(const float* __restrict__ Kqk, const float* __restrict__ Kqr) {
    __shared__ float sq[cD], sk[cD];
    __shared__ float sKa[cND * cKH], sKb[cND * cKH];
    int bl = blockIdx.x;
    int t  = threadIdx.x;
    for (int c = t; c < cD; c += 256) {
        sq[c] = g_q[(size_t)bl * cD + c];
        sk[c] = g_k[(size_t)bl * cD + c];
    }
    for (int c = t; c < cND * cKH; c += 256) { sKa[c] = Kqk[c]; sKb[c] = Kqr[c]; }
    __syncthreads();
    if (t < cH * cND) {
        int h = t / cND, d = t % cND;
        float s1 = 0.f, s2 = 0.f;
#pragma unroll
        for (int k = 0; k < cKH; k++) {
            s1 += sq[h * cKH + k] * sKa[d * cKH + k];
            s2 += sk[h * cKH + k] * sKb[d * cKH + k];
        }
        int b = bl / cL, l = bl % cL;
        size_t off = ((size_t)(b * cH + (size_t)h) * cL + l) * cND + d;
        g_qE[off] = s1;
        g_kE[off] = s2;
    }
}

// ------------------------- fused flash attention (bf16 3-term MMA) ----------
#define SC_STRIDE 520
__global__ __launch_bounds__(256) void flash_attn_kernel() {
    extern __shared__ char smraw[];
    float* SC            = (float*)smraw;
    unsigned char* DIDX  = (unsigned char*)(SC + 64 * SC_STRIDE);
    float* QS   = (float*)(DIDX + 64 * 512);
    float* KS   = QS + 2112;
    float* QES  = KS + 2112;
    float* KES  = QES + 1024;
    float* HIST = KES + 1024;
    float* RMAX = HIST + 4096;
    float* REDS = RMAX + 128;
    float* RINV = REDS + 256;
    float* VSUM = RINV + 64;
    float* SKR  = VSUM + 448;

    int bh = blockIdx.y;
    int b  = bh >> 4, h = bh & 15;
    int l0 = blockIdx.x * 64;
    int t  = threadIdx.x;
    int lane = t & 31, wid = t >> 5;
    int wm = wid & 3, wn = wid >> 2;
    int gr = lane >> 2, t4 = lane & 3;

#pragma unroll
    for (int r = 0; r < 8; r++) {
        int l = r * 8 + (t >> 5), k = t & 31;
        QS[l * 33 + k] = g_q[(size_t)(b * cL + l0 + l) * cD + h * 32 + k];
    }
    for (int idx = t; idx < 64 * cND; idx += 256) {
        int l = idx / cND, d = idx % cND;
        QES[l * 16 + d] = g_qE[((size_t)bh * cL + l0 + l) * cND + d];
    }
    {
        const int4* src = (const int4*)(g_didx + ((size_t)b * cL + l0) * cL);
        for (int idx = t; idx < 2048; idx += 256) ((int4*)DIDX)[idx] = src[idx];
    }
    for (int idx = t; idx < cND * 32; idx += 256) VSUM[idx] = g_Vsum[idx];
    if (t < cND) SKR[t] = g_sumKkr[t];
    __syncthreads();

    uint32_t qh[2][4], ql[2][4];
    {
        int r0 = wm * 16 + gr;
#pragma unroll
        for (int ks = 0; ks < 2; ks++) {
            int k0 = ks * 16 + 2 * t4;
            split2(QS[r0 * 33 + k0],       QS[r0 * 33 + k0 + 1],       qh[ks][0], ql[ks][0]);
            split2(QS[(r0 + 8) * 33 + k0], QS[(r0 + 8) * 33 + k0 + 1], qh[ks][1], ql[ks][1]);
            split2(QS[r0 * 33 + k0 + 8],   QS[r0 * 33 + k0 + 9],       qh[ks][2], ql[ks][2]);
            split2(QS[(r0 + 8) * 33 + k0 + 8], QS[(r0 + 8) * 33 + k0 + 9], qh[ks][3], ql[ks][3]);
        }
    }
    float mx0 = -1e30f, mx1 = -1e30f;

    for (int xt = 0; xt < 8; xt++) {
        int x0 = xt * 64;
#pragma unroll
        for (int r = 0; r < 8; r++) {
            int i = r * 8 + (t >> 5), k = t & 31;
            KS[i * 33 + k] = g_k[(size_t)(b * cL + x0 + i) * cD + h * 32 + k];
        }
        for (int idx = t; idx < 64 * cND; idx += 256) {
            int i2 = idx / cND, d = idx % cND;
            KES[i2 * 16 + d] = g_kE[((size_t)bh * cL + x0 + i2) * cND + d];
        }
        __syncthreads();

        float acc[4][4] = {};
#pragma unroll
        for (int jn = 0; jn < 4; jn++) {
            int c0 = wn * 32 + jn * 8 + gr;
#pragma unroll
            for (int ks = 0; ks < 2; ks++) {
                int k0 = ks * 16 + 2 * t4;
                uint32_t kb[2], kl[2];
                split2(KS[c0 * 33 + k0],     KS[c0 * 33 + k0 + 1], kb[0], kl[0]);
                split2(KS[c0 * 33 + k0 + 8], KS[c0 * 33 + k0 + 9], kb[1], kl[1]);
                mma_bf16(acc[jn], ql[ks], kb);
                mma_bf16(acc[jn], qh[ks], kl);
                mma_bf16(acc[jn], qh[ks], kb);
            }
        }
        int r0 = wm * 16 + gr;
#pragma unroll
        for (int jn = 0; jn < 4; jn++) {
            int cbase = wn * 32 + jn * 8 + 2 * t4;
#pragma unroll
            for (int q = 0; q < 4; q++) {
                int row = (q & 2) ? r0 + 8 : r0;
                int ct  = cbase + (q & 1);
                int col = x0 + ct;
                int d = DIDX[row * 512 + col];
                float e = (acc[jn][q] + QES[row * 16 + d] + KES[ct * 16 + d] + SKR[d]) * SCALEF;
                SC[row * SC_STRIDE + col] = e;
                if (q & 2) mx1 = fmaxf(mx1, e); else mx0 = fmaxf(mx0, e);
            }
        }
        __syncthreads();
    }
    mx0 = fmaxf(mx0, __shfl_xor_sync(0xffffffffu, mx0, 1));
    mx0 = fmaxf(mx0, __shfl_xor_sync(0xffffffffu, mx0, 2));
    mx1 = fmaxf(mx1, __shfl_xor_sync(0xffffffffu, mx1, 1));
    mx1 = fmaxf(mx1, __shfl_xor_sync(0xffffffffu, mx1, 2));
    if (t4 == 0) {
        RMAX[(wm * 16 + gr) + 64 * wn]     = mx0;
        RMAX[(wm * 16 + gr + 8) + 64 * wn] = mx1;
    }
    __syncthreads();

    {
        int r = t >> 2, j = t & 3;
        float m = fmaxf(RMAX[r], RMAX[r + 64]);
#pragma unroll
        for (int d = 0; d < 16; d++) HIST[d * 256 + t] = 0.f;
        float s = 0.f;
        for (int i = 0; i < 128; i++) {
            int x = 4 * i + j;
            float p = __expf(SC[r * SC_STRIDE + x] - m);
            SC[r * SC_STRIDE + x] = p;
            s += p;
            int d = DIDX[r * 512 + x];
            HIST[d * 256 + t] += p;
        }
        REDS[t] = s;
        __syncthreads();
        if (t < 64) RINV[t] = 1.0f / (REDS[4 * t] + REDS[4 * t + 1] + REDS[4 * t + 2] + REDS[4 * t + 3]);
        for (int idx = t; idx < 64 * cND; idx += 256) {
            int d = idx >> 6, r2 = idx & 63;
            QES[r2 * 16 + d] = HIST[d * 256 + 4 * r2]     + HIST[d * 256 + 4 * r2 + 1]
                             + HIST[d * 256 + 4 * r2 + 2] + HIST[d * 256 + 4 * r2 + 3];
        }
        __syncthreads();
    }

    {
        float zc[2][4] = {};
        float* VS = KS;
        for (int xt = 0; xt < 8; xt++) {
            int x0 = xt * 64;
#pragma unroll
            for (int r = 0; r < 8; r++) {
                int i = r * 8 + (t >> 5), k = t & 31;
                VS[i * 33 + k] = g_v[(size_t)(b * cL + x0 + i) * cD + h * 32 + k];
            }
            __syncthreads();
            int r0 = wm * 16 + gr;
#pragma unroll
            for (int ks = 0; ks < 4; ks++) {
                int kk = x0 + ks * 16 + 2 * t4;
                uint32_t pah[4], pal[4];
                split2(SC[r0 * SC_STRIDE + kk],           SC[r0 * SC_STRIDE + kk + 1],           pah[0], pal[0]);
                split2(SC[(r0 + 8) * SC_STRIDE + kk],     SC[(r0 + 8) * SC_STRIDE + kk + 1],     pah[1], pal[1]);
                split2(SC[r0 * SC_STRIDE + kk + 8],       SC[r0 * SC_STRIDE + kk + 9],           pah[2], pal[2]);
                split2(SC[(r0 + 8) * SC_STRIDE + kk + 8], SC[(r0 + 8) * SC_STRIDE + kk + 9],     pah[3], pal[3]);
                int kv = ks * 16 + 2 * t4;
#pragma unroll
                for (int jn = 0; jn < 2; jn++) {
                    int col = wn * 16 + jn * 8 + gr;
                    uint32_t vh[2], vl[2];
                    split2(VS[kv * 33 + col],       VS[(kv + 1) * 33 + col], vh[0], vl[0]);
                    split2(VS[(kv + 8) * 33 + col], VS[(kv + 9) * 33 + col], vh[1], vl[1]);
                    mma_bf16(zc[jn], pal, vh);
                    mma_bf16(zc[jn], pah, vl);
                    mma_bf16(zc[jn], pah, vh);
                }
            }
            __syncthreads();
        }
        int r0 = wm * 16 + gr;
#pragma unroll
        for (int jn = 0; jn < 2; jn++) {
            int col0 = wn * 16 + jn * 8 + 2 * t4;
#pragma unroll
            for (int qq = 0; qq < 2; qq++) {
                int row = r0 + qq * 8;
                float z0 = zc[jn][qq * 2 + 0], z1 = zc[jn][qq * 2 + 1];
#pragma unroll
                for (int d = 0; d < cND; d++) {
                    float hv = QES[row * 16 + d];
                    z0 += hv * VSUM[d * 32 + col0];
                    z1 += hv * VSUM[d * 32 + col0 + 1];
                }
                float ri = RINV[row];
                *(float2*)&g_z[(size_t)(b * cL + l0 + row) * cD + h * 32 + col0] =
                    make_float2(z0 * ri, z1 * ri);
            }
        }
    }
}

// ------------------------- layernorm of (X + R1 + R2) -----------------------
__global__ void ln3_kernel(const float* __restrict__ X, const float* __restrict__ R1,
                           const float* __restrict__ R2,
                           const float* __restrict__ gg, const float* __restrict__ bb,
                           float* __restrict__ out) {
    int row = blockIdx.x, t = threadIdx.x;
    float lv[4];
    float s = 0.f;
#pragma unroll
    for (int r = 0; r < 4; r++) {
        int c = t + 128 * r;
        lv[r] = X[(size_t)row * cD + c] + R1[(size_t)row * cD + c] + R2[(size_t)row * cD + c];
        s += lv[r];
    }
    __shared__ float red[128];
    red[t] = s; __syncthreads();
#pragma unroll
    for (int st = 64; st > 0; st >>= 1) { if (t < st) red[t] += red[t + st]; __syncthreads(); }
    float mu = red[0] * (1.0f / cD);
    __syncthreads();
    float vs = 0.f;
#pragma unroll
    for (int r = 0; r < 4; r++) { float d = lv[r] - mu; vs += d * d; }
    red[t] = vs; __syncthreads();
#pragma unroll
    for (int st = 64; st > 0; st >>= 1) { if (t < st) red[t] += red[t + st]; __syncthreads(); }
    float inv = rsqrtf(red[0] * (1.0f / cD) + 1e-5f);
#pragma unroll
    for (int r = 0; r < 4; r++) {
        int c = t + 128 * r;
        out[(size_t)row * cD + c] = (lv[r] - mu) * inv * gg[c] + bb[c];
    }
}

// ------------------------- head ---------------------------------------------
__global__ void head_kernel(const float* __restrict__ Wm1, const float* __restrict__ bm1,
                            const float* __restrict__ Wm2, const float* __restrict__ bm2,
                            float* __restrict__ out) {
    int b = blockIdx.x, t = threadIdx.x;
    __shared__ float pooled[cD];
    float s = 0.f;
    for (int l = 0; l < cL; l++) s += g_h[(size_t)(b * cL + l) * cD + t];
    pooled[t] = s;
    __syncthreads();
    float r = bm1[t];
    for (int d = 0; d < cD; d++) r += pooled[d] * Wm1[(size_t)d * cM + t];
    r = fmaxf(r, 0.f);
    __shared__ float red[512];
    red[t] = r * Wm2[t];
    __syncthreads();
#pragma unroll
    for (int st = 256; st > 0; st >>= 1) { if (t < st) red[t] += red[t + st]; __syncthreads(); }
    if (t == 0) out[b] = red[0] + bm2[0];
}

// ===========================================================================
extern "C" void kernel_launch(void* const* d_in, const int* in_sizes, int n_in,
                              void* d_out, int out_size) {
    const int*   cell_types = (const int*)  d_in[0];
    const float* distances  = (const float*)d_in[1];
    const float* cell_emb   = (const float*)d_in[2];
    const float* Kqk = (const float*)d_in[3];
    const float* Kqr = (const float*)d_in[4];
    const float* Kkr = (const float*)d_in[5];
    const float* Vqk = (const float*)d_in[6];
    const float* Vqr = (const float*)d_in[7];
    const float* Vkr = (const float*)d_in[8];

    int iWq = 9, ibq, iWk, ibk, iWv, ibv, iWo, ibo;
    if (in_sizes[10] == cNL * cD) {
        ibq = 10; iWk = 11; ibk = 12; iWv = 13; ibv = 14; iWo = 15; ibo = 16;
    } else {
        iWk = 10; iWv = 11; iWo = 12; ibq = 13; ibk = 14; ibv = 15; ibo = 16;
    }
    const float* Wq = (const float*)d_in[iWq];
    const float* bq = (const float*)d_in[ibq];
    const float* Wk = (const float*)d_in[iWk];
    const float* bk = (const float*)d_in[ibk];
    const float* Wv = (const float*)d_in[iWv];
    const float* bv = (const float*)d_in[ibv];
    const float* Wo = (const float*)d_in[iWo];
    const float* bo = (const float*)d_in[ibo];
    const float* W1  = (const float*)d_in[17];
    const float* b1  = (const float*)d_in[18];
    const float* W2  = (const float*)d_in[19];
    const float* b2  = (const float*)d_in[20];
    const float* g1  = (const float*)d_in[21];
    const float* be1 = (const float*)d_in[22];
    const float* g2  = (const float*)d_in[23];
    const float* be2 = (const float*)d_in[24];
    const float* Wm1 = (const float*)d_in[25];
    const float* bm1 = (const float*)d_in[26];
    const float* Wm2 = (const float*)d_in[27];
    const float* bm2 = (const float*)d_in[28];
    float* out = (float*)d_out;

    float *p_h, *p_q, *p_k, *p_v, *p_z, *p_o, *p_o2, *p_h2, *p_f, *p_zb;
    uint32_t* p_wp;
    cudaGetSymbolAddress((void**)&p_h,  g_h);
    cudaGetSymbolAddress((void**)&p_q,  g_q);
    cudaGetSymbolAddress((void**)&p_k,  g_k);
    cudaGetSymbolAddress((void**)&p_v,  g_v);
    cudaGetSymbolAddress((void**)&p_z,  g_z);
    cudaGetSymbolAddress((void**)&p_o,  g_o);
    cudaGetSymbolAddress((void**)&p_o2, g_o2);
    cudaGetSymbolAddress((void**)&p_h2, g_h2);
    cudaGetSymbolAddress((void**)&p_f,  g_f);
    cudaGetSymbolAddress((void**)&p_zb, g_zb);
    cudaGetSymbolAddress((void**)&p_wp, g_wp);

    static const int FLASH_SMEM =
        (64 * SC_STRIDE) * 4 + 64 * 512 +
        (2112 + 2112 + 1024 + 1024 + 4096 + 128 + 256 + 64 + 448 + 16) * 4;
    cudaFuncSetAttribute(flash_attn_kernel,
                         cudaFuncAttributeMaxDynamicSharedMemorySize, FLASH_SMEM);

    const int SM128 = 3 * (A_FLOATS + 16 * 136) * 4;
    const int SM64  = 3 * (A_FLOATS + 16 * 72) * 4;
    cudaFuncSetAttribute(mma_gemm<128, false, true>,
                         cudaFuncAttributeMaxDynamicSharedMemorySize, SM128);
    cudaFuncSetAttribute(mma_gemm<128, true, false>,
                         cudaFuncAttributeMaxDynamicSharedMemorySize, SM128);
    cudaFuncSetAttribute(mma_gemm<64, false, true>,
                         cudaFuncAttributeMaxDynamicSharedMemorySize, SM64);

    didx_kernel<<<(cB * cL * cL) / 256, 256>>>(distances);
    embed_kernel<<<cBL, 256>>>(cell_types, cell_emb);
    prep_kernel<<<1, 448>>>(Kkr, Vqk, Vqr, Vkr);

    dim3 wt(256);
    wconv_kernel<<<dim3(16, 32, 8), wt>>>(Wq, p_wp + 0,       cD, cD, (size_t)cD * cD, WPL);
    wconv_kernel<<<dim3(16, 32, 8), wt>>>(Wk, p_wp + 262144,  cD, cD, (size_t)cD * cD, WPL);
    wconv_kernel<<<dim3(16, 32, 8), wt>>>(Wv, p_wp + 524288,  cD, cD, (size_t)cD * cD, WPL);
    wconv_kernel<<<dim3(16, 32, 8), wt>>>(Wo, p_wp + 786432,  cD, cD, (size_t)cD * cD, WPL);
    wconv_kernel<<<dim3(64, 32, 8), wt>>>(W1, p_wp + 1048576, cD, cFF, (size_t)cD * cFF, WPL);
    wconv_kernel<<<dim3(16, 128, 8), wt>>>(W2, p_wp + 2097152, cFF, cD, (size_t)cFF * cD, WPL);

    dim3 gQKV(cD / 128, cBL / 64, 3);       // (4,32,3)  = 384 CTAs
    dim3 gSK (cD / 64, cBL / 64, 2);        // (8,32,2)  = 512 CTAs
    dim3 gFF1(cFF / 128, cBL / 64);         // (16,32)   = 512 CTAs
    dim3 gFlash(cL / 64, cB * cH);          // 512 CTAs

    for (int ly = 0; ly < cNL; ly++) {
        const uint32_t* wp = p_wp + (size_t)ly * WPL;
        const float* bqp = bq + (size_t)ly * cD;
        const float* bkp = bk + (size_t)ly * cD;
        const float* bvp = bv + (size_t)ly * cD;
        const float* bop = bo + (size_t)ly * cD;
        const float* b1p = b1 + (size_t)ly * cFF;
        const float* b2p = b2 + (size_t)ly * cD;
        const float* g1p  = g1  + (size_t)ly * cD;
        const float* be1p = be1 + (size_t)ly * cD;
        const float* g2p  = g2  + (size_t)ly * cD;
        const float* be2p = be2 + (size_t)ly * cD;

        GArgs aQKV = { p_h, wp + 0, wp + 262144, wp + 524288,
                       bqp, bkp, bvp, p_q, p_k, p_v };
        mma_gemm<128, false, true><<<gQKV, 256, SM128>>>(aQKV, cBL, cD, cD, cD, 0, 131072);

        qke_kernel<<<cBL, 256>>>(Kqk, Kqr);
        flash_attn_kernel<<<gFlash, 256, FLASH_SMEM>>>();

        GArgs aO = { p_z, wp + 786432, wp + 786432 + 65536, wp + 786432 + 65536,
                     bop, p_zb, p_zb, p_o, p_o2, p_o2 };
        mma_gemm<64, false, true><<<gSK, 256, SM64>>>(aO, cBL, cD, 256, cD, 256, 131072);
        ln3_kernel<<<cBL, 128>>>(p_h, p_o, p_o2, g1p, be1p, p_h2);

        GArgs aF1 = { p_h2, wp + 1048576, 0, 0, b1p, 0, 0, p_f, 0, 0 };
        mma_gemm<128, true, false><<<gFF1, 256, SM128>>>(aF1, cBL, cFF, cD, cD, 0, 524288);

        GArgs aF2 = { p_f, wp + 2097152, wp + 2097152 + 262144, wp + 2097152 + 262144,
                      b2p, p_zb, p_zb, p_o, p_o2, p_o2 };
        mma_gemm<64, false, true><<<gSK, 256, SM64>>>(aF2, cBL, cD, 1024, cFF, 1024, 524288);
        ln3_kernel<<<cBL, 128>>>(p_h2, p_o, p_o2, g2p, be2p, p_h);
    }

    head_kernel<<<cB, 512>>>(Wm1, bm1, Wm2, bm2, out);
}

// round 12
// speedup vs baseline: 1.0497x; 1.0497x over previous
#include <cuda_runtime.h>
#include <math.h>
#include <stdint.h>

#define cB 4
#define cL 512
#define cD 512
#define cH 16
#define cKH 32
#define cFF 2048
#define cNL 8
#define cND 14
#define cM 512
#define cBL (cB*cL)
#define SCALEF 0.17677669529663687f  // 1/sqrt(32)

// ------------------------- scratch (static device globals) ------------------
__device__ float g_h [cBL*cD];
__device__ float g_q [cBL*cD];
__device__ float g_k [cBL*cD];
__device__ float g_v [cBL*cD];
__device__ float g_z [cBL*cD];
__device__ float g_o [cBL*cD];
__device__ float g_o2[cBL*cD];
__device__ float g_h2[cBL*cD];
__device__ float g_f [cBL*cFF];
__device__ float g_qE [cB*cH*cL*cND];
__device__ float g_kE [cB*cH*cL*cND];
__device__ unsigned char g_didx[cB*cL*cL];
__device__ float g_Vsum[cND*cKH];
__device__ float g_sumKkr[cND];
__device__ float g_zb[cD];          // zero bias (never written)

// packed bf16 hi/lo weights per layer (u32 offsets):
//   wq @0, wk @262144, wv @524288, wo @786432, w1 @1048576, w2 @2097152
#define WPL 3145728
__device__ uint32_t g_wp[(size_t)cNL * WPL];

// ------------------------- helpers ------------------------------------------
__device__ __forceinline__ uint32_t smem_u32(const void* p) {
    uint32_t a;
    asm("{ .reg .u64 t; cvta.to.shared.u64 t, %1; cvt.u32.u64 %0, t; }" : "=r"(a) : "l"(p));
    return a;
}
__device__ __forceinline__ void cpasync16(uint32_t dst, const void* src) {
    asm volatile("cp.async.cg.shared.global [%0], [%1], 16;" :: "r"(dst), "l"(src));
}
#define CP_COMMIT() asm volatile("cp.async.commit_group;" ::: "memory")
#define CP_WAIT1()  asm volatile("cp.async.wait_group 1;" ::: "memory")

// split (x0,x1) into packed bf16x2 hi + lo, low half = x0
__device__ __forceinline__ void split2(float x0, float x1, uint32_t& hi, uint32_t& lo) {
    uint32_t h;
    asm("cvt.rn.bf16x2.f32 %0, %1, %2;" : "=r"(h) : "f"(x1), "f"(x0));
    float h0 = __uint_as_float(h << 16);
    float h1 = __uint_as_float(h & 0xffff0000u);
    uint32_t l;
    asm("cvt.rn.bf16x2.f32 %0, %1, %2;" : "=r"(l) : "f"(x1 - h1), "f"(x0 - h0));
    hi = h; lo = l;
}
__device__ __forceinline__ void mma_bf16(float* c, const uint32_t* a, const uint32_t* b) {
    asm volatile(
        "mma.sync.aligned.m16n8k16.row.col.f32.bf16.bf16.f32 "
        "{%0,%1,%2,%3}, {%4,%5,%6,%7}, {%8,%9}, {%0,%1,%2,%3};\n"
        : "+f"(c[0]), "+f"(c[1]), "+f"(c[2]), "+f"(c[3])
        : "r"(a[0]), "r"(a[1]), "r"(a[2]), "r"(a[3]), "r"(b[0]), "r"(b[1]));
}

// ------------------------- weight conversion pre-pass ------------------------
__global__ void wconv_kernel(const float* __restrict__ src, uint32_t* __restrict__ dst,
                             int K, int N, size_t sStride, size_t dStride) {
    int ly = blockIdx.z;
    const float* s = src + (size_t)ly * sStride;
    uint32_t* d = dst + (size_t)ly * dStride;
    int t = threadIdx.x;
    int n  = blockIdx.x * 32 + (t & 31);
    int k2 = blockIdx.y * 8 + (t >> 5);
    float w0 = s[(size_t)(2 * k2) * N + n];
    float w1 = s[(size_t)(2 * k2 + 1) * N + n];
    uint32_t hi, lo;
    split2(w0, w1, hi, lo);
    size_t loSz = (size_t)(K / 2) * N;
    d[(size_t)k2 * N + n] = hi;
    d[loSz + (size_t)k2 * N + n] = lo;
}

// ------------------------- bf16 3-term tensor-core GEMM ---------------------
// BM=128, BK=32 (2 k-steps per barrier), warps 4(M)x2(N). B pre-packed hi/lo.
struct GArgs {
    const float* A;
    const uint32_t* W0; const uint32_t* W1; const uint32_t* W2;
    const float* c0; const float* c1; const float* c2;
    float* C0; float* C1; float* C2;
};

#define A_STRIDE 36
#define A_FLOATS (128 * A_STRIDE)

template<int BN, bool GELU, bool TRIPLE>
__global__ __launch_bounds__(256, 2) void mma_gemm(GArgs args, int Md, int Nd, int Kd,
                                                   int ldA, int aStep, int loOff) {
    constexpr int BSTR = BN + 8;                    // u32 stride, conflict-free
    constexpr int STAGE = A_FLOATS + 32 * BSTR;     // floats per stage
    constexpr int NT = BN / 16;
    constexpr int BCH = 16 * BN / 4;                // float4 chunks per hi array
    extern __shared__ float smem[];
    uint32_t smb = smem_u32(smem);

    int t = threadIdx.x;
    const float* A = args.A;
    const uint32_t* W; const float* bias; float* C;
    if (TRIPLE) {
        int z = blockIdx.z;
        A   += (size_t)z * aStep;
        W    = (z == 0) ? args.W0 : (z == 1) ? args.W1 : args.W2;
        bias = (z == 0) ? args.c0 : (z == 1) ? args.c1 : args.c2;
        C    = (z == 0) ? args.C0 : (z == 1) ? args.C1 : args.C2;
    } else { W = args.W0; bias = args.c0; C = args.C0; }

    int m0 = blockIdx.y * 128, n0 = blockIdx.x * BN;

    auto issue = [&](int ch, int s) {
        int k0  = ch << 5;   // fp32 k base (32 per chunk)
        int k2b = ch << 4;   // packed row base (16 per chunk)
        uint32_t sa = smb + (uint32_t)(s * STAGE) * 4;
        uint32_t sb = sa + A_FLOATS * 4;
#pragma unroll
        for (int it = 0; it < 4; it++) {            // A: 128x32 = 1024 float4
            int idx = t + it * 256;
            int row = idx >> 3, c4 = (idx & 7) << 2;
            cpasync16(sa + (uint32_t)(row * A_STRIDE + c4) * 4,
                      &A[(size_t)(m0 + row) * ldA + k0 + c4]);
        }
#pragma unroll
        for (int it = 0; it < (2 * BCH) / 256; it++) {
            int idx = t + it * 256;
            int arr = (idx >= BCH) ? 1 : 0;
            int ci  = idx - arr * BCH;
            int row = ci / (BN / 4), c4 = (ci % (BN / 4)) << 2;
            cpasync16(sb + (uint32_t)((arr * 16 + row) * BSTR + c4) * 4,
                      &W[(size_t)(arr ? loOff : 0) + (size_t)(k2b + row) * Nd + n0 + c4]);
        }
    };

    int lane = t & 31, wid = t >> 5;
    int wm = wid & 3, wn = wid >> 2;
    int gr = lane >> 2, t4 = lane & 3;

    float c[2][NT][4];
#pragma unroll
    for (int i = 0; i < 2; i++)
#pragma unroll
        for (int j = 0; j < NT; j++)
#pragma unroll
            for (int q = 0; q < 4; q++) c[i][j][q] = 0.f;

    int nc = Kd >> 5;
    issue(0, 0); CP_COMMIT();
    issue(1, 1); CP_COMMIT();

    for (int ch = 0; ch < nc; ch++) {
        CP_WAIT1();
        __syncthreads();
        if (ch + 2 < nc) issue(ch + 2, (ch + 2) % 3);
        CP_COMMIT();

        const float* sA = smem + (ch % 3) * STAGE;
        const uint32_t* sBhi = (const uint32_t*)(sA + A_FLOATS);
        const uint32_t* sBlo = sBhi + 16 * BSTR;

#pragma unroll
        for (int ks = 0; ks < 2; ks++) {
            int kc = ks * 16 + 2 * t4;
            uint32_t ah[2][4], al[2][4];
#pragma unroll
            for (int i = 0; i < 2; i++) {
                int r0 = wm * 32 + i * 16 + gr;
                float2 p00 = *(const float2*)&sA[r0 * A_STRIDE + kc];
                float2 p10 = *(const float2*)&sA[(r0 + 8) * A_STRIDE + kc];
                float2 p01 = *(const float2*)&sA[r0 * A_STRIDE + kc + 8];
                float2 p11 = *(const float2*)&sA[(r0 + 8) * A_STRIDE + kc + 8];
                split2(p00.x, p00.y, ah[i][0], al[i][0]);
                split2(p10.x, p10.y, ah[i][1], al[i][1]);
                split2(p01.x, p01.y, ah[i][2], al[i][2]);
                split2(p11.x, p11.y, ah[i][3], al[i][3]);
            }
#pragma unroll
            for (int j = 0; j < NT; j++) {
                int n = wn * (BN / 2) + j * 8 + gr;
                uint32_t bh[2], bl[2];
                bh[0] = sBhi[(ks * 8 + t4) * BSTR + n];
                bh[1] = sBhi[(ks * 8 + t4 + 4) * BSTR + n];
                bl[0] = sBlo[(ks * 8 + t4) * BSTR + n];
                bl[1] = sBlo[(ks * 8 + t4 + 4) * BSTR + n];
#pragma unroll
                for (int i = 0; i < 2; i++) {
                    mma_bf16(c[i][j], al[i], bh);
                    mma_bf16(c[i][j], ah[i], bl);
                    mma_bf16(c[i][j], ah[i], bh);
                }
            }
        }
    }

#pragma unroll
    for (int i = 0; i < 2; i++) {
        int rb = m0 + wm * 32 + i * 16 + gr;
#pragma unroll
        for (int j = 0; j < NT; j++) {
            int col = n0 + wn * (BN / 2) + j * 8 + t4 * 2;
            float2 bb = *(const float2*)&bias[col];
            float v0 = c[i][j][0] + bb.x, v1 = c[i][j][1] + bb.y;
            float v2 = c[i][j][2] + bb.x, v3 = c[i][j][3] + bb.y;
            if (GELU) {
                v0 = 0.5f * v0 * (1.0f + erff(v0 * 0.70710678118654752f));
                v1 = 0.5f * v1 * (1.0f + erff(v1 * 0.70710678118654752f));
                v2 = 0.5f * v2 * (1.0f + erff(v2 * 0.70710678118654752f));
                v3 = 0.5f * v3 * (1.0f + erff(v3 * 0.70710678118654752f));
            }
            *(float2*)&C[(size_t)rb * Nd + col] = make_float2(v0, v1);
            *(float2*)&C[(size_t)(rb + 8) * Nd + col] = make_float2(v2, v3);
        }
    }
}

// ------------------------- distance bucketize -------------------------------
__global__ void didx_kernel(const float* __restrict__ dist) {
    int i = blockIdx.x * blockDim.x + threadIdx.x;
    float d = dist[i];
    int idx = 0;
#pragma unroll
    for (int j = 1; j <= 14; j++) idx += (10.0f * (float)j < d) ? 1 : 0;
    if (idx > 13) idx = 13;
    g_didx[i] = (unsigned char)idx;
}

// ------------------------- embedding gather ---------------------------------
__global__ void embed_kernel(const int* __restrict__ ct, const float* __restrict__ emb) {
    int row = blockIdx.x;
    int c0  = ct[row];
    for (int c = threadIdx.x; c < cD; c += blockDim.x)
        g_h[(size_t)row * cD + c] = emb[(size_t)c0 * cD + c];
}

// ------------------------- tiny precompute ----------------------------------
__global__ void prep_kernel(const float* __restrict__ Kkr,
                            const float* __restrict__ Vqk,
                            const float* __restrict__ Vqr,
                            const float* __restrict__ Vkr) {
    int t = threadIdx.x;
    if (t < cND * cKH) g_Vsum[t] = Vqk[t] + Vqr[t] + Vkr[t];
    if (t < cND) {
        float s = 0.f;
        for (int k = 0; k < cKH; k++) s += Kkr[t * cKH + k];
        g_sumKkr[t] = s;
    }
}

// ------------------------- qE / kE ------------------------------------------
__global__ void qke_kernel(const float* __restrict__ Kqk, const float* __restrict__ Kqr) {
    __shared__ float sq[cD], sk[cD];
    __shared__ float sKa[cND * cKH], sKb[cND * cKH];
    int bl = blockIdx.x;
    int t  = threadIdx.x;
    for (int c = t; c < cD; c += 256) {
        sq[c] = g_q[(size_t)bl * cD + c];
        sk[c] = g_k[(size_t)bl * cD + c];
    }
    for (int c = t; c < cND * cKH; c += 256) { sKa[c] = Kqk[c]; sKb[c] = Kqr[c]; }
    __syncthreads();
    if (t < cH * cND) {
        int h = t / cND, d = t % cND;
        float s1 = 0.f, s2 = 0.f;
#pragma unroll
        for (int k = 0; k < cKH; k++) {
            s1 += sq[h * cKH + k] * sKa[d * cKH + k];
            s2 += sk[h * cKH + k] * sKb[d * cKH + k];
        }
        int b = bl / cL, l = bl % cL;
        size_t off = ((size_t)(b * cH + (size_t)h) * cL + l) * cND + d;
        g_qE[off] = s1;
        g_kE[off] = s2;
    }
}

// ------------------------- fused flash attention (bf16 3-term MMA) ----------
#define SC_STRIDE 520
__global__ __launch_bounds__(256) void flash_attn_kernel() {
    extern __shared__ char smraw[];
    float* SC            = (float*)smraw;
    unsigned char* DIDX  = (unsigned char*)(SC + 64 * SC_STRIDE);
    float* QS   = (float*)(DIDX + 64 * 512);
    float* KS   = QS + 2112;
    float* QES  = KS + 2112;
    float* KES  = QES + 1024;
    float* HIST = KES + 1024;
    float* RMAX = HIST + 4096;
    float* REDS = RMAX + 128;
    float* RINV = REDS + 256;
    float* VSUM = RINV + 64;
    float* SKR  = VSUM + 448;

    int bh = blockIdx.y;
    int b  = bh >> 4, h = bh & 15;
    int l0 = blockIdx.x * 64;
    int t  = threadIdx.x;
    int lane = t & 31, wid = t >> 5;
    int wm = wid & 3, wn = wid >> 2;
    int gr = lane >> 2, t4 = lane & 3;

#pragma unroll
    for (int r = 0; r < 8; r++) {
        int l = r * 8 + (t >> 5), k = t & 31;
        QS[l * 33 + k] = g_q[(size_t)(b * cL + l0 + l) * cD + h * 32 + k];
    }
    for (int idx = t; idx < 64 * cND; idx += 256) {
        int l = idx / cND, d = idx % cND;
        QES[l * 16 + d] = g_qE[((size_t)bh * cL + l0 + l) * cND + d];
    }
    {
        const int4* src = (const int4*)(g_didx + ((size_t)b * cL + l0) * cL);
        for (int idx = t; idx < 2048; idx += 256) ((int4*)DIDX)[idx] = src[idx];
    }
    for (int idx = t; idx < cND * 32; idx += 256) VSUM[idx] = g_Vsum[idx];
    if (t < cND) SKR[t] = g_sumKkr[t];
    __syncthreads();

    uint32_t qh[2][4], ql[2][4];
    {
        int r0 = wm * 16 + gr;
#pragma unroll
        for (int ks = 0; ks < 2; ks++) {
            int k0 = ks * 16 + 2 * t4;
            split2(QS[r0 * 33 + k0],       QS[r0 * 33 + k0 + 1],       qh[ks][0], ql[ks][0]);
            split2(QS[(r0 + 8) * 33 + k0], QS[(r0 + 8) * 33 + k0 + 1], qh[ks][1], ql[ks][1]);
            split2(QS[r0 * 33 + k0 + 8],   QS[r0 * 33 + k0 + 9],       qh[ks][2], ql[ks][2]);
            split2(QS[(r0 + 8) * 33 + k0 + 8], QS[(r0 + 8) * 33 + k0 + 9], qh[ks][3], ql[ks][3]);
        }
    }
    float mx0 = -1e30f, mx1 = -1e30f;

    for (int xt = 0; xt < 8; xt++) {
        int x0 = xt * 64;
#pragma unroll
        for (int r = 0; r < 8; r++) {
            int i = r * 8 + (t >> 5), k = t & 31;
            KS[i * 33 + k] = g_k[(size_t)(b * cL + x0 + i) * cD + h * 32 + k];
        }
        for (int idx = t; idx < 64 * cND; idx += 256) {
            int i2 = idx / cND, d = idx % cND;
            KES[i2 * 16 + d] = g_kE[((size_t)bh * cL + x0 + i2) * cND + d];
        }
        __syncthreads();

        float acc[4][4] = {};
#pragma unroll
        for (int jn = 0; jn < 4; jn++) {
            int c0 = wn * 32 + jn * 8 + gr;
#pragma unroll
            for (int ks = 0; ks < 2; ks++) {
                int k0 = ks * 16 + 2 * t4;
                uint32_t kb[2], kl[2];
                split2(KS[c0 * 33 + k0],     KS[c0 * 33 + k0 + 1], kb[0], kl[0]);
                split2(KS[c0 * 33 + k0 + 8], KS[c0 * 33 + k0 + 9], kb[1], kl[1]);
                mma_bf16(acc[jn], ql[ks], kb);
                mma_bf16(acc[jn], qh[ks], kl);
                mma_bf16(acc[jn], qh[ks], kb);
            }
        }
        int r0 = wm * 16 + gr;
#pragma unroll
        for (int jn = 0; jn < 4; jn++) {
            int cbase = wn * 32 + jn * 8 + 2 * t4;
#pragma unroll
            for (int q = 0; q < 4; q++) {
                int row = (q & 2) ? r0 + 8 : r0;
                int ct  = cbase + (q & 1);
                int col = x0 + ct;
                int d = DIDX[row * 512 + col];
                float e = (acc[jn][q] + QES[row * 16 + d] + KES[ct * 16 + d] + SKR[d]) * SCALEF;
                SC[row * SC_STRIDE + col] = e;
                if (q & 2) mx1 = fmaxf(mx1, e); else mx0 = fmaxf(mx0, e);
            }
        }
        __syncthreads();
    }
    mx0 = fmaxf(mx0, __shfl_xor_sync(0xffffffffu, mx0, 1));
    mx0 = fmaxf(mx0, __shfl_xor_sync(0xffffffffu, mx0, 2));
    mx1 = fmaxf(mx1, __shfl_xor_sync(0xffffffffu, mx1, 1));
    mx1 = fmaxf(mx1, __shfl_xor_sync(0xffffffffu, mx1, 2));
    if (t4 == 0) {
        RMAX[(wm * 16 + gr) + 64 * wn]     = mx0;
        RMAX[(wm * 16 + gr + 8) + 64 * wn] = mx1;
    }
    __syncthreads();

    {
        int r = t >> 2, j = t & 3;
        float m = fmaxf(RMAX[r], RMAX[r + 64]);
#pragma unroll
        for (int d = 0; d < 16; d++) HIST[d * 256 + t] = 0.f;
        float s = 0.f;
        for (int i = 0; i < 128; i++) {
            int x = 4 * i + j;
            float p = __expf(SC[r * SC_STRIDE + x] - m);
            SC[r * SC_STRIDE + x] = p;
            s += p;
            int d = DIDX[r * 512 + x];
            HIST[d * 256 + t] += p;
        }
        REDS[t] = s;
        __syncthreads();
        if (t < 64) RINV[t] = 1.0f / (REDS[4 * t] + REDS[4 * t + 1] + REDS[4 * t + 2] + REDS[4 * t + 3]);
        for (int idx = t; idx < 64 * cND; idx += 256) {
            int d = idx >> 6, r2 = idx & 63;
            QES[r2 * 16 + d] = HIST[d * 256 + 4 * r2]     + HIST[d * 256 + 4 * r2 + 1]
                             + HIST[d * 256 + 4 * r2 + 2] + HIST[d * 256 + 4 * r2 + 3];
        }
        __syncthreads();
    }

    {
        float zc[2][4] = {};
        float* VS = KS;
        for (int xt = 0; xt < 8; xt++) {
            int x0 = xt * 64;
#pragma unroll
            for (int r = 0; r < 8; r++) {
                int i = r * 8 + (t >> 5), k = t & 31;
                VS[i * 33 + k] = g_v[(size_t)(b * cL + x0 + i) * cD + h * 32 + k];
            }
            __syncthreads();
            int r0 = wm * 16 + gr;
#pragma unroll
            for (int ks = 0; ks < 4; ks++) {
                int kk = x0 + ks * 16 + 2 * t4;
                uint32_t pah[4], pal[4];
                split2(SC[r0 * SC_STRIDE + kk],           SC[r0 * SC_STRIDE + kk + 1],           pah[0], pal[0]);
                split2(SC[(r0 + 8) * SC_STRIDE + kk],     SC[(r0 + 8) * SC_STRIDE + kk + 1],     pah[1], pal[1]);
                split2(SC[r0 * SC_STRIDE + kk + 8],       SC[r0 * SC_STRIDE + kk + 9],           pah[2], pal[2]);
                split2(SC[(r0 + 8) * SC_STRIDE + kk + 8], SC[(r0 + 8) * SC_STRIDE + kk + 9],     pah[3], pal[3]);
                int kv = ks * 16 + 2 * t4;
#pragma unroll
                for (int jn = 0; jn < 2; jn++) {
                    int col = wn * 16 + jn * 8 + gr;
                    uint32_t vh[2], vl[2];
                    split2(VS[kv * 33 + col],       VS[(kv + 1) * 33 + col], vh[0], vl[0]);
                    split2(VS[(kv + 8) * 33 + col], VS[(kv + 9) * 33 + col], vh[1], vl[1]);
                    mma_bf16(zc[jn], pal, vh);
                    mma_bf16(zc[jn], pah, vl);
                    mma_bf16(zc[jn], pah, vh);
                }
            }
            __syncthreads();
        }
        int r0 = wm * 16 + gr;
#pragma unroll
        for (int jn = 0; jn < 2; jn++) {
            int col0 = wn * 16 + jn * 8 + 2 * t4;
#pragma unroll
            for (int qq = 0; qq < 2; qq++) {
                int row = r0 + qq * 8;
                float z0 = zc[jn][qq * 2 + 0], z1 = zc[jn][qq * 2 + 1];
#pragma unroll
                for (int d = 0; d < cND; d++) {
                    float hv = QES[row * 16 + d];
                    z0 += hv * VSUM[d * 32 + col0];
                    z1 += hv * VSUM[d * 32 + col0 + 1];
                }
                float ri = RINV[row];
                *(float2*)&g_z[(size_t)(b * cL + l0 + row) * cD + h * 32 + col0] =
                    make_float2(z0 * ri, z1 * ri);
            }
        }
    }
}

// ------------------------- layernorm of (X + R1 + R2) -----------------------
__global__ void ln3_kernel(const float* __restrict__ X, const float* __restrict__ R1,
                           const float* __restrict__ R2,
                           const float* __restrict__ gg, const float* __restrict__ bb,
                           float* __restrict__ out) {
    int row = blockIdx.x, t = threadIdx.x;
    float lv[4];
    float s = 0.f;
#pragma unroll
    for (int r = 0; r < 4; r++) {
        int c = t + 128 * r;
        lv[r] = X[(size_t)row * cD + c] + R1[(size_t)row * cD + c] + R2[(size_t)row * cD + c];
        s += lv[r];
    }
    __shared__ float red[128];
    red[t] = s; __syncthreads();
#pragma unroll
    for (int st = 64; st > 0; st >>= 1) { if (t < st) red[t] += red[t + st]; __syncthreads(); }
    float mu = red[0] * (1.0f / cD);
    __syncthreads();
    float vs = 0.f;
#pragma unroll
    for (int r = 0; r < 4; r++) { float d = lv[r] - mu; vs += d * d; }
    red[t] = vs; __syncthreads();
#pragma unroll
    for (int st = 64; st > 0; st >>= 1) { if (t < st) red[t] += red[t + st]; __syncthreads(); }
    float inv = rsqrtf(red[0] * (1.0f / cD) + 1e-5f);
#pragma unroll
    for (int r = 0; r < 4; r++) {
        int c = t + 128 * r;
        out[(size_t)row * cD + c] = (lv[r] - mu) * inv * gg[c] + bb[c];
    }
}

// ------------------------- head ---------------------------------------------
__global__ void head_kernel(const float* __restrict__ Wm1, const float* __restrict__ bm1,
                            const float* __restrict__ Wm2, const float* __restrict__ bm2,
                            float* __restrict__ out) {
    int b = blockIdx.x, t = threadIdx.x;
    __shared__ float pooled[cD];
    float s = 0.f;
    for (int l = 0; l < cL; l++) s += g_h[(size_t)(b * cL + l) * cD + t];
    pooled[t] = s;
    __syncthreads();
    float r = bm1[t];
    for (int d = 0; d < cD; d++) r += pooled[d] * Wm1[(size_t)d * cM + t];
    r = fmaxf(r, 0.f);
    __shared__ float red[512];
    red[t] = r * Wm2[t];
    __syncthreads();
#pragma unroll
    for (int st = 256; st > 0; st >>= 1) { if (t < st) red[t] += red[t + st]; __syncthreads(); }
    if (t == 0) out[b] = red[0] + bm2[0];
}

// ===========================================================================
extern "C" void kernel_launch(void* const* d_in, const int* in_sizes, int n_in,
                              void* d_out, int out_size) {
    const int*   cell_types = (const int*)  d_in[0];
    const float* distances  = (const float*)d_in[1];
    const float* cell_emb   = (const float*)d_in[2];
    const float* Kqk = (const float*)d_in[3];
    const float* Kqr = (const float*)d_in[4];
    const float* Kkr = (const float*)d_in[5];
    const float* Vqk = (const float*)d_in[6];
    const float* Vqr = (const float*)d_in[7];
    const float* Vkr = (const float*)d_in[8];

    int iWq = 9, ibq, iWk, ibk, iWv, ibv, iWo, ibo;
    if (in_sizes[10] == cNL * cD) {
        ibq = 10; iWk = 11; ibk = 12; iWv = 13; ibv = 14; iWo = 15; ibo = 16;
    } else {
        iWk = 10; iWv = 11; iWo = 12; ibq = 13; ibk = 14; ibv = 15; ibo = 16;
    }
    const float* Wq = (const float*)d_in[iWq];
    const float* bq = (const float*)d_in[ibq];
    const float* Wk = (const float*)d_in[iWk];
    const float* bk = (const float*)d_in[ibk];
    const float* Wv = (const float*)d_in[iWv];
    const float* bv = (const float*)d_in[ibv];
    const float* Wo = (const float*)d_in[iWo];
    const float* bo = (const float*)d_in[ibo];
    const float* W1  = (const float*)d_in[17];
    const float* b1  = (const float*)d_in[18];
    const float* W2  = (const float*)d_in[19];
    const float* b2  = (const float*)d_in[20];
    const float* g1  = (const float*)d_in[21];
    const float* be1 = (const float*)d_in[22];
    const float* g2  = (const float*)d_in[23];
    const float* be2 = (const float*)d_in[24];
    const float* Wm1 = (const float*)d_in[25];
    const float* bm1 = (const float*)d_in[26];
    const float* Wm2 = (const float*)d_in[27];
    const float* bm2 = (const float*)d_in[28];
    float* out = (float*)d_out;

    float *p_h, *p_q, *p_k, *p_v, *p_z, *p_o, *p_o2, *p_h2, *p_f, *p_zb;
    uint32_t* p_wp;
    cudaGetSymbolAddress((void**)&p_h,  g_h);
    cudaGetSymbolAddress((void**)&p_q,  g_q);
    cudaGetSymbolAddress((void**)&p_k,  g_k);
    cudaGetSymbolAddress((void**)&p_v,  g_v);
    cudaGetSymbolAddress((void**)&p_z,  g_z);
    cudaGetSymbolAddress((void**)&p_o,  g_o);
    cudaGetSymbolAddress((void**)&p_o2, g_o2);
    cudaGetSymbolAddress((void**)&p_h2, g_h2);
    cudaGetSymbolAddress((void**)&p_f,  g_f);
    cudaGetSymbolAddress((void**)&p_zb, g_zb);
    cudaGetSymbolAddress((void**)&p_wp, g_wp);

    static const int FLASH_SMEM =
        (64 * SC_STRIDE) * 4 + 64 * 512 +
        (2112 + 2112 + 1024 + 1024 + 4096 + 128 + 256 + 64 + 448 + 16) * 4;
    cudaFuncSetAttribute(flash_attn_kernel,
                         cudaFuncAttributeMaxDynamicSharedMemorySize, FLASH_SMEM);

    const int SM128 = 3 * (A_FLOATS + 32 * 136) * 4;   // 107,520 B
    const int SM64  = 3 * (A_FLOATS + 32 * 72) * 4;    //  82,944 B
    cudaFuncSetAttribute(mma_gemm<128, false, true>,
                         cudaFuncAttributeMaxDynamicSharedMemorySize, SM128);
    cudaFuncSetAttribute(mma_gemm<128, true, false>,
                         cudaFuncAttributeMaxDynamicSharedMemorySize, SM128);
    cudaFuncSetAttribute(mma_gemm<64, false, true>,
                         cudaFuncAttributeMaxDynamicSharedMemorySize, SM64);

    didx_kernel<<<(cB * cL * cL) / 256, 256>>>(distances);
    embed_kernel<<<cBL, 256>>>(cell_types, cell_emb);
    prep_kernel<<<1, 448>>>(Kkr, Vqk, Vqr, Vkr);

    dim3 wt(256);
    wconv_kernel<<<dim3(16, 32, 8), wt>>>(Wq, p_wp + 0,       cD, cD, (size_t)cD * cD, WPL);
    wconv_kernel<<<dim3(16, 32, 8), wt>>>(Wk, p_wp + 262144,  cD, cD, (size_t)cD * cD, WPL);
    wconv_kernel<<<dim3(16, 32, 8), wt>>>(Wv, p_wp + 524288,  cD, cD, (size_t)cD * cD, WPL);
    wconv_kernel<<<dim3(16, 32, 8), wt>>>(Wo, p_wp + 786432,  cD, cD, (size_t)cD * cD, WPL);
    wconv_kernel<<<dim3(64, 32, 8), wt>>>(W1, p_wp + 1048576, cD, cFF, (size_t)cD * cFF, WPL);
    wconv_kernel<<<dim3(16, 128, 8), wt>>>(W2, p_wp + 2097152, cFF, cD, (size_t)cFF * cD, WPL);

    dim3 gQKV(cD / 128, cBL / 128, 3);      // 192 CTAs
    dim3 gSK (cD / 64, cBL / 128, 2);       // 256 CTAs (split-K O-proj / FF2)
    dim3 gFF1(cFF / 128, cBL / 128);        // 256 CTAs
    dim3 gFlash(cL / 64, cB * cH);          // 512 CTAs

    for (int ly = 0; ly < cNL; ly++) {
        const uint32_t* wp = p_wp + (size_t)ly * WPL;
        const float* bqp = bq + (size_t)ly * cD;
        const float* bkp = bk + (size_t)ly * cD;
        const float* bvp = bv + (size_t)ly * cD;
        const float* bop = bo + (size_t)ly * cD;
        const float* b1p = b1 + (size_t)ly * cFF;
        const float* b2p = b2 + (size_t)ly * cD;
        const float* g1p  = g1  + (size_t)ly * cD;
        const float* be1p = be1 + (size_t)ly * cD;
        const float* g2p  = g2  + (size_t)ly * cD;
        const float* be2p = be2 + (size_t)ly * cD;

        GArgs aQKV = { p_h, wp + 0, wp + 262144, wp + 524288,
                       bqp, bkp, bvp, p_q, p_k, p_v };
        mma_gemm<128, false, true><<<gQKV, 256, SM128>>>(aQKV, cBL, cD, cD, cD, 0, 131072);

        qke_kernel<<<cBL, 256>>>(Kqk, Kqr);
        flash_attn_kernel<<<gFlash, 256, FLASH_SMEM>>>();

        // O-proj split-K=2: halves of K=512 (z=1 packed rows start at k2=128)
        GArgs aO = { p_z, wp + 786432, wp + 786432 + 65536, wp + 786432 + 65536,
                     bop, p_zb, p_zb, p_o, p_o2, p_o2 };
        mma_gemm<64, false, true><<<gSK, 256, SM64>>>(aO, cBL, cD, 256, cD, 256, 131072);
        ln3_kernel<<<cBL, 128>>>(p_h, p_o, p_o2, g1p, be1p, p_h2);

        GArgs aF1 = { p_h2, wp + 1048576, 0, 0, b1p, 0, 0, p_f, 0, 0 };
        mma_gemm<128, true, false><<<gFF1, 256, SM128>>>(aF1, cBL, cFF, cD, cD, 0, 524288);

        // FF2 split-K=2: halves of K=2048 (z=1 packed rows start at k2=512)
        GArgs aF2 = { p_f, wp + 2097152, wp + 2097152 + 262144, wp + 2097152 + 262144,
                      b2p, p_zb, p_zb, p_o, p_o2, p_o2 };
        mma_gemm<64, false, true><<<gSK, 256, SM64>>>(aF2, cBL, cD, 1024, cFF, 1024, 524288);
        ln3_kernel<<<cBL, 128>>>(p_h2, p_o, p_o2, g2p, be2p, p_h);
    }

    head_kernel<<<cB, 512>>>(Wm1, bm1, Wm2, bm2, out);
}

// round 15
// speedup vs baseline: 1.2364x; 1.1778x over previous
#include <cuda_runtime.h>
#include <math.h>
#include <stdint.h>

#define cB 4
#define cL 512
#define cD 512
#define cH 16
#define cKH 32
#define cFF 2048
#define cNL 8
#define cND 14
#define cM 512
#define cBL (cB*cL)
#define SCALEF 0.17677669529663687f  // 1/sqrt(32)

// ------------------------- scratch (static device globals) ------------------
__device__ float g_h [cBL*cD];
__device__ float g_q [cBL*cD];
__device__ float g_k [cBL*cD];
__device__ float g_v [cBL*cD];
__device__ float g_z [cBL*cD];
__device__ float g_o [cBL*cD];
__device__ float g_o2[cBL*cD];
__device__ float g_h2[cBL*cD];
__device__ float g_f [cBL*cFF];
__device__ float g_qE [cB*cH*cL*cND];
__device__ float g_kE [cB*cH*cL*cND];
__device__ unsigned char g_didx[cB*cL*cL];
__device__ float g_Vsum[cND*cKH];
__device__ float g_sumKkr[cND];
__device__ float g_zb[cD];          // zero bias (never written)

#define WPL 3145728
__device__ uint32_t g_wp[(size_t)cNL * WPL];

// ------------------------- helpers ------------------------------------------
__device__ __forceinline__ uint32_t smem_u32(const void* p) {
    uint32_t a;
    asm("{ .reg .u64 t; cvta.to.shared.u64 t, %1; cvt.u32.u64 %0, t; }" : "=r"(a) : "l"(p));
    return a;
}
__device__ __forceinline__ void cpasync16(uint32_t dst, const void* src) {
    asm volatile("cp.async.cg.shared.global [%0], [%1], 16;" :: "r"(dst), "l"(src));
}
#define CP_COMMIT() asm volatile("cp.async.commit_group;" ::: "memory")
#define CP_WAIT1()  asm volatile("cp.async.wait_group 1;" ::: "memory")
#define CP_WAIT0()  asm volatile("cp.async.wait_group 0;" ::: "memory")

// split (x0,x1) into packed bf16x2 hi + lo, low half = x0
__device__ __forceinline__ void split2(float x0, float x1, uint32_t& hi, uint32_t& lo) {
    uint32_t h;
    asm("cvt.rn.bf16x2.f32 %0, %1, %2;" : "=r"(h) : "f"(x1), "f"(x0));
    float h0 = __uint_as_float(h << 16);
    float h1 = __uint_as_float(h & 0xffff0000u);
    uint32_t l;
    asm("cvt.rn.bf16x2.f32 %0, %1, %2;" : "=r"(l) : "f"(x1 - h1), "f"(x0 - h0));
    hi = h; lo = l;
}
__device__ __forceinline__ void mma_bf16(float* c, const uint32_t* a, const uint32_t* b) {
    asm volatile(
        "mma.sync.aligned.m16n8k16.row.col.f32.bf16.bf16.f32 "
        "{%0,%1,%2,%3}, {%4,%5,%6,%7}, {%8,%9}, {%0,%1,%2,%3};\n"
        : "+f"(c[0]), "+f"(c[1]), "+f"(c[2]), "+f"(c[3])
        : "r"(a[0]), "r"(a[1]), "r"(a[2]), "r"(a[3]), "r"(b[0]), "r"(b[1]));
}

// ------------------------- weight conversion pre-pass ------------------------
__global__ void wconv_kernel(const float* __restrict__ src, uint32_t* __restrict__ dst,
                             int K, int N, size_t sStride, size_t dStride) {
    int ly = blockIdx.z;
    const float* s = src + (size_t)ly * sStride;
    uint32_t* d = dst + (size_t)ly * dStride;
    int t = threadIdx.x;
    int n  = blockIdx.x * 32 + (t & 31);
    int k2 = blockIdx.y * 8 + (t >> 5);
    float w0 = s[(size_t)(2 * k2) * N + n];
    float w1 = s[(size_t)(2 * k2 + 1) * N + n];
    uint32_t hi, lo;
    split2(w0, w1, hi, lo);
    size_t loSz = (size_t)(K / 2) * N;
    d[(size_t)k2 * N + n] = hi;
    d[loSz + (size_t)k2 * N + n] = lo;
}

// ------------------------- bf16 3-term tensor-core GEMM (BK=32) --------------
struct GArgs {
    const float* A;
    const uint32_t* W0; const uint32_t* W1; const uint32_t* W2;
    const float* c0; const float* c1; const float* c2;
    float* C0; float* C1; float* C2;
};

#define A_STRIDE 36
#define A_FLOATS (128 * A_STRIDE)

template<int BN, bool GELU, bool TRIPLE>
__global__ __launch_bounds__(256, 2) void mma_gemm(GArgs args, int Md, int Nd, int Kd,
                                                   int ldA, int aStep, int loOff) {
    constexpr int BSTR = BN + 8;
    constexpr int STAGE = A_FLOATS + 32 * BSTR;
    constexpr int NT = BN / 16;
    constexpr int BCH = 16 * BN / 4;
    extern __shared__ float smem[];
    uint32_t smb = smem_u32(smem);

    int t = threadIdx.x;
    const float* A = args.A;
    const uint32_t* W; const float* bias; float* C;
    if (TRIPLE) {
        int z = blockIdx.z;
        A   += (size_t)z * aStep;
        W    = (z == 0) ? args.W0 : (z == 1) ? args.W1 : args.W2;
        bias = (z == 0) ? args.c0 : (z == 1) ? args.c1 : args.c2;
        C    = (z == 0) ? args.C0 : (z == 1) ? args.C1 : args.C2;
    } else { W = args.W0; bias = args.c0; C = args.C0; }

    int m0 = blockIdx.y * 128, n0 = blockIdx.x * BN;

    auto issue = [&](int ch, int s) {
        int k0  = ch << 5;
        int k2b = ch << 4;
        uint32_t sa = smb + (uint32_t)(s * STAGE) * 4;
        uint32_t sb = sa + A_FLOATS * 4;
#pragma unroll
        for (int it = 0; it < 4; it++) {
            int idx = t + it * 256;
            int row = idx >> 3, c4 = (idx & 7) << 2;
            cpasync16(sa + (uint32_t)(row * A_STRIDE + c4) * 4,
                      &A[(size_t)(m0 + row) * ldA + k0 + c4]);
        }
#pragma unroll
        for (int it = 0; it < (2 * BCH) / 256; it++) {
            int idx = t + it * 256;
            int arr = (idx >= BCH) ? 1 : 0;
            int ci  = idx - arr * BCH;
            int row = ci / (BN / 4), c4 = (ci % (BN / 4)) << 2;
            cpasync16(sb + (uint32_t)((arr * 16 + row) * BSTR + c4) * 4,
                      &W[(size_t)(arr ? loOff : 0) + (size_t)(k2b + row) * Nd + n0 + c4]);
        }
    };

    int lane = t & 31, wid = t >> 5;
    int wm = wid & 3, wn = wid >> 2;
    int gr = lane >> 2, t4 = lane & 3;

    float c[2][NT][4];
#pragma unroll
    for (int i = 0; i < 2; i++)
#pragma unroll
        for (int j = 0; j < NT; j++)
#pragma unroll
            for (int q = 0; q < 4; q++) c[i][j][q] = 0.f;

    int nc = Kd >> 5;
    issue(0, 0); CP_COMMIT();
    issue(1, 1); CP_COMMIT();

    for (int ch = 0; ch < nc; ch++) {
        CP_WAIT1();
        __syncthreads();
        if (ch + 2 < nc) issue(ch + 2, (ch + 2) % 3);
        CP_COMMIT();

        const float* sA = smem + (ch % 3) * STAGE;
        const uint32_t* sBhi = (const uint32_t*)(sA + A_FLOATS);
        const uint32_t* sBlo = sBhi + 16 * BSTR;

#pragma unroll
        for (int ks = 0; ks < 2; ks++) {
            int kc = ks * 16 + 2 * t4;
            uint32_t ah[2][4], al[2][4];
#pragma unroll
            for (int i = 0; i < 2; i++) {
                int r0 = wm * 32 + i * 16 + gr;
                float2 p00 = *(const float2*)&sA[r0 * A_STRIDE + kc];
                float2 p10 = *(const float2*)&sA[(r0 + 8) * A_STRIDE + kc];
                float2 p01 = *(const float2*)&sA[r0 * A_STRIDE + kc + 8];
                float2 p11 = *(const float2*)&sA[(r0 + 8) * A_STRIDE + kc + 8];
                split2(p00.x, p00.y, ah[i][0], al[i][0]);
                split2(p10.x, p10.y, ah[i][1], al[i][1]);
                split2(p01.x, p01.y, ah[i][2], al[i][2]);
                split2(p11.x, p11.y, ah[i][3], al[i][3]);
            }
#pragma unroll
            for (int j = 0; j < NT; j++) {
                int n = wn * (BN / 2) + j * 8 + gr;
                uint32_t bh[2], bl[2];
                bh[0] = sBhi[(ks * 8 + t4) * BSTR + n];
                bh[1] = sBhi[(ks * 8 + t4 + 4) * BSTR + n];
                bl[0] = sBlo[(ks * 8 + t4) * BSTR + n];
                bl[1] = sBlo[(ks * 8 + t4 + 4) * BSTR + n];
#pragma unroll
                for (int i = 0; i < 2; i++) {
                    mma_bf16(c[i][j], al[i], bh);
                    mma_bf16(c[i][j], ah[i], bl);
                    mma_bf16(c[i][j], ah[i], bh);
                }
            }
        }
    }

#pragma unroll
    for (int i = 0; i < 2; i++) {
        int rb = m0 + wm * 32 + i * 16 + gr;
#pragma unroll
        for (int j = 0; j < NT; j++) {
            int col = n0 + wn * (BN / 2) + j * 8 + t4 * 2;
            float2 bb = *(const float2*)&bias[col];
            float v0 = c[i][j][0] + bb.x, v1 = c[i][j][1] + bb.y;
            float v2 = c[i][j][2] + bb.x, v3 = c[i][j][3] + bb.y;
            if (GELU) {
                v0 = 0.5f * v0 * (1.0f + erff(v0 * 0.70710678118654752f));
                v1 = 0.5f * v1 * (1.0f + erff(v1 * 0.70710678118654752f));
                v2 = 0.5f * v2 * (1.0f + erff(v2 * 0.70710678118654752f));
                v3 = 0.5f * v3 * (1.0f + erff(v3 * 0.70710678118654752f));
            }
            *(float2*)&C[(size_t)rb * Nd + col] = make_float2(v0, v1);
            *(float2*)&C[(size_t)(rb + 8) * Nd + col] = make_float2(v2, v3);
        }
    }
}

// ------------------------- distance bucketize -------------------------------
__global__ void didx_kernel(const float* __restrict__ dist) {
    int i = blockIdx.x * blockDim.x + threadIdx.x;
    float d = dist[i];
    int idx = 0;
#pragma unroll
    for (int j = 1; j <= 14; j++) idx += (10.0f * (float)j < d) ? 1 : 0;
    if (idx > 13) idx = 13;
    g_didx[i] = (unsigned char)idx;
}

// ------------------------- embedding gather ---------------------------------
__global__ void embed_kernel(const int* __restrict__ ct, const float* __restrict__ emb) {
    int row = blockIdx.x;
    int c0  = ct[row];
    for (int c = threadIdx.x; c < cD; c += blockDim.x)
        g_h[(size_t)row * cD + c] = emb[(size_t)c0 * cD + c];
}

// ------------------------- tiny precompute ----------------------------------
__global__ void prep_kernel(const float* __restrict__ Kkr,
                            const float* __restrict__ Vqk,
                            const float* __restrict__ Vqr,
                            const float* __restrict__ Vkr) {
    int t = threadIdx.x;
    if (t < cND * cKH) g_Vsum[t] = Vqk[t] + Vqr[t] + Vkr[t];
    if (t < cND) {
        float s = 0.f;
        for (int k = 0; k < cKH; k++) s += Kkr[t * cKH + k];
        g_sumKkr[t] = s;
    }
}

// ------------------------- qE / kE ------------------------------------------
__global__ void qke_kernel(const float* __restrict__ Kqk, const float* __restrict__ Kqr) {
    __shared__ float sq[cD], sk[cD];
    __shared__ float sKa[cND * cKH], sKb[cND * cKH];
    int bl = blockIdx.x;
    int t  = threadIdx.x;
    for (int c = t; c < cD; c += 256) {
        sq[c] = g_q[(size_t)bl * cD + c];
        sk[c] = g_k[(size_t)bl * cD + c];
    }
    for (int c = t; c < cND * cKH; c += 256) { sKa[c] = Kqk[c]; sKb[c] = Kqr[c]; }
    __syncthreads();
    if (t < cH * cND) {
        int h = t / cND, d = t % cND;
        float s1 = 0.f, s2 = 0.f;
#pragma unroll
        for (int k = 0; k < cKH; k++) {
            s1 += sq[h * cKH + k] * sKa[d * cKH + k];
            s2 += sk[h * cKH + k] * sKb[d * cKH + k];
        }
        int b = bl / cL, l = bl % cL;
        size_t off = ((size_t)(b * cH + (size_t)h) * cL + l) * cND + d;
        g_qE[off] = s1;
        g_kE[off] = s2;
    }
}

// ------------------------- fused flash attention ----------------------------
// bf16 3-term MMA; cp.async double-buffered K/V tiles; vectorized softmax.
#define SC_STRIDE 520
#define KV_STR 36
#define KV_BUF (64 * KV_STR)
__global__ __launch_bounds__(256) void flash_attn_kernel() {
    extern __shared__ char smraw[];
    float* SC            = (float*)smraw;                         // 64*520
    unsigned char* DIDX  = (unsigned char*)(SC + 64 * SC_STRIDE); // 64*512 B
    float* QS   = (float*)(DIDX + 64 * 512);  // 2112
    float* KV   = QS + 2112;                  // 2 x 2304
    float* QES  = KV + 2 * KV_BUF;            // 1024
    float* KES  = QES + 1024;                 // 896 (single buffer, packed [64][14])
    float* HIST = KES + 896;                  // 14*256 = 3584
    float* RMAX = HIST + 3584;                // 128
    float* REDS = RMAX + 128;                 // 256
    float* RINV = REDS + 256;                 // 64
    float* VSUM = RINV + 64;                  // 448
    float* SKR  = VSUM + 448;                 // 16
    uint32_t kvB  = smem_u32(KV);
    uint32_t kesB = smem_u32(KES);

    int bh = blockIdx.y;
    int b  = bh >> 4, h = bh & 15;
    int l0 = blockIdx.x * 64;
    int t  = threadIdx.x;
    int lane = t & 31, wid = t >> 5;
    int wm = wid & 3, wn = wid >> 2;
    int gr = lane >> 2, t4 = lane & 3;

    auto issueK = [&](int xt, int bufi) {
        int x0 = xt * 64;
        uint32_t dst = kvB + (uint32_t)(bufi * KV_BUF) * 4;
#pragma unroll
        for (int it = 0; it < 2; it++) {
            int idx = t + it * 256;
            int row = idx >> 3, c4 = (idx & 7) << 2;
            cpasync16(dst + (uint32_t)(row * KV_STR + c4) * 4,
                      &g_k[(size_t)(b * cL + x0 + row) * cD + h * 32 + c4]);
        }
    };
    auto issueV = [&](int xt, int bufi) {
        int x0 = xt * 64;
        uint32_t dst = kvB + (uint32_t)(bufi * KV_BUF) * 4;
#pragma unroll
        for (int it = 0; it < 2; it++) {
            int idx = t + it * 256;
            int row = idx >> 3, c4 = (idx & 7) << 2;
            cpasync16(dst + (uint32_t)(row * KV_STR + c4) * 4,
                      &g_v[(size_t)(b * cL + x0 + row) * cD + h * 32 + c4]);
        }
    };

    // ---- preload Q, qE, didx strip, Vsum, sumKkr; prefetch K tile 0 ----
    issueK(0, 0); CP_COMMIT();
#pragma unroll
    for (int r = 0; r < 8; r++) {
        int l = r * 8 + (t >> 5), k = t & 31;
        QS[l * 33 + k] = g_q[(size_t)(b * cL + l0 + l) * cD + h * 32 + k];
    }
    for (int idx = t; idx < 64 * cND; idx += 256) {
        int l = idx / cND, d = idx % cND;
        QES[l * 16 + d] = g_qE[((size_t)bh * cL + l0 + l) * cND + d];
    }
    {
        const int4* src = (const int4*)(g_didx + ((size_t)b * cL + l0) * cL);
        for (int idx = t; idx < 2048; idx += 256) ((int4*)DIDX)[idx] = src[idx];
    }
    for (int idx = t; idx < cND * 32; idx += 256) VSUM[idx] = g_Vsum[idx];
    if (t < cND) SKR[t] = g_sumKkr[t];
    __syncthreads();

    // ---- Q fragments (hoisted) ----
    uint32_t qh[2][4], ql[2][4];
    {
        int r0 = wm * 16 + gr;
#pragma unroll
        for (int ks = 0; ks < 2; ks++) {
            int k0 = ks * 16 + 2 * t4;
            split2(QS[r0 * 33 + k0],       QS[r0 * 33 + k0 + 1],       qh[ks][0], ql[ks][0]);
            split2(QS[(r0 + 8) * 33 + k0], QS[(r0 + 8) * 33 + k0 + 1], qh[ks][1], ql[ks][1]);
            split2(QS[r0 * 33 + k0 + 8],   QS[r0 * 33 + k0 + 9],       qh[ks][2], ql[ks][2]);
            split2(QS[(r0 + 8) * 33 + k0 + 8], QS[(r0 + 8) * 33 + k0 + 9], qh[ks][3], ql[ks][3]);
        }
    }
    float mx0 = -1e30f, mx1 = -1e30f;

    // ---- phase 1: scores, double-buffered K; kE loaded per tile (sync) ----
    for (int xt = 0; xt < 8; xt++) {
        int x0 = xt * 64;
        // kE strip for this tile (small, coalesced)
        if (t < 224)
            *(float4*)&KES[t * 4] = *(const float4*)&g_kE[((size_t)bh * cL + x0) * cND + t * 4];
        if (xt + 1 < 8) { issueK(xt + 1, (xt + 1) & 1); CP_COMMIT(); CP_WAIT1(); }
        else            { CP_WAIT0(); }
        __syncthreads();
        const float* KS_ = KV + (xt & 1) * KV_BUF;

        float acc[4][4] = {};
#pragma unroll
        for (int jn = 0; jn < 4; jn++) {
            int c0 = wn * 32 + jn * 8 + gr;
#pragma unroll
            for (int ks = 0; ks < 2; ks++) {
                int k0 = ks * 16 + 2 * t4;
                uint32_t kb[2], kl[2];
                split2(KS_[c0 * KV_STR + k0],     KS_[c0 * KV_STR + k0 + 1], kb[0], kl[0]);
                split2(KS_[c0 * KV_STR + k0 + 8], KS_[c0 * KV_STR + k0 + 9], kb[1], kl[1]);
                mma_bf16(acc[jn], ql[ks], kb);
                mma_bf16(acc[jn], qh[ks], kl);
                mma_bf16(acc[jn], qh[ks], kb);
            }
        }
        int r0 = wm * 16 + gr;
#pragma unroll
        for (int jn = 0; jn < 4; jn++) {
            int cbase = wn * 32 + jn * 8 + 2 * t4;
#pragma unroll
            for (int q = 0; q < 4; q++) {
                int row = (q & 2) ? r0 + 8 : r0;
                int ct  = cbase + (q & 1);
                int col = x0 + ct;
                int d = DIDX[row * 512 + col];
                float e = (acc[jn][q] + QES[row * 16 + d] + KES[ct * cND + d] + SKR[d]) * SCALEF;
                SC[row * SC_STRIDE + col] = e;
                if (q & 2) mx1 = fmaxf(mx1, e); else mx0 = fmaxf(mx0, e);
            }
        }
        __syncthreads();
    }
    mx0 = fmaxf(mx0, __shfl_xor_sync(0xffffffffu, mx0, 1));
    mx0 = fmaxf(mx0, __shfl_xor_sync(0xffffffffu, mx0, 2));
    mx1 = fmaxf(mx1, __shfl_xor_sync(0xffffffffu, mx1, 1));
    mx1 = fmaxf(mx1, __shfl_xor_sync(0xffffffffu, mx1, 2));
    if (t4 == 0) {
        RMAX[(wm * 16 + gr) + 64 * wn]     = mx0;
        RMAX[(wm * 16 + gr + 8) + 64 * wn] = mx1;
    }
    // prefetch V tile 0 (overlaps entire softmax pass)
    issueV(0, 0); CP_COMMIT();
    __syncthreads();

    // ---- phase 2: exp + row-sum + bucket histogram (vectorized) ----
    {
        int r = t >> 2, j = t & 3;
        float m = fmaxf(RMAX[r], RMAX[r + 64]);
#pragma unroll
        for (int d = 0; d < cND; d++) HIST[d * 256 + t] = 0.f;
        float s = 0.f;
        float4* scrow = (float4*)&SC[r * SC_STRIDE + j * 128];
        const uchar4* drow = (const uchar4*)&DIDX[r * 512 + j * 128];
        for (int i = 0; i < 32; i++) {
            float4 p = scrow[i];
            uchar4 d4 = drow[i];
            p.x = __expf(p.x - m); p.y = __expf(p.y - m);
            p.z = __expf(p.z - m); p.w = __expf(p.w - m);
            s += (p.x + p.y) + (p.z + p.w);
            HIST[d4.x * 256 + t] += p.x;
            HIST[d4.y * 256 + t] += p.y;
            HIST[d4.z * 256 + t] += p.z;
            HIST[d4.w * 256 + t] += p.w;
            scrow[i] = p;
        }
        REDS[t] = s;
        __syncthreads();
        if (t < 64) RINV[t] = 1.0f / (REDS[4 * t] + REDS[4 * t + 1] + REDS[4 * t + 2] + REDS[4 * t + 3]);
        for (int idx = t; idx < 64 * cND; idx += 256) {
            int d = idx >> 6, r2 = idx & 63;
            QES[r2 * 16 + d] = HIST[d * 256 + 4 * r2]     + HIST[d * 256 + 4 * r2 + 1]
                             + HIST[d * 256 + 4 * r2 + 2] + HIST[d * 256 + 4 * r2 + 3];
        }
        __syncthreads();
    }

    // ---- phase 3: z = P@V (MMA) + hist@Vsum, normalized; double-buffered V --
    {
        float zc[2][4] = {};
        for (int xt = 0; xt < 8; xt++) {
            if (xt + 1 < 8) { issueV(xt + 1, (xt + 1) & 1); CP_COMMIT(); CP_WAIT1(); }
            else            { CP_WAIT0(); }
            __syncthreads();
            const float* VS_ = KV + (xt & 1) * KV_BUF;
            int x0 = xt * 64;
            int r0 = wm * 16 + gr;
#pragma unroll
            for (int ks = 0; ks < 4; ks++) {
                int kk = x0 + ks * 16 + 2 * t4;
                uint32_t pah[4], pal[4];
                split2(SC[r0 * SC_STRIDE + kk],           SC[r0 * SC_STRIDE + kk + 1],           pah[0], pal[0]);
                split2(SC[(r0 + 8) * SC_STRIDE + kk],     SC[(r0 + 8) * SC_STRIDE + kk + 1],     pah[1], pal[1]);
                split2(SC[r0 * SC_STRIDE + kk + 8],       SC[r0 * SC_STRIDE + kk + 9],           pah[2], pal[2]);
                split2(SC[(r0 + 8) * SC_STRIDE + kk + 8], SC[(r0 + 8) * SC_STRIDE + kk + 9],     pah[3], pal[3]);
                int kv = ks * 16 + 2 * t4;
#pragma unroll
                for (int jn = 0; jn < 2; jn++) {
                    int col = wn * 16 + jn * 8 + gr;
                    uint32_t vh[2], vl[2];
                    split2(VS_[kv * KV_STR + col],       VS_[(kv + 1) * KV_STR + col], vh[0], vl[0]);
                    split2(VS_[(kv + 8) * KV_STR + col], VS_[(kv + 9) * KV_STR + col], vh[1], vl[1]);
                    mma_bf16(zc[jn], pal, vh);
                    mma_bf16(zc[jn], pah, vl);
                    mma_bf16(zc[jn], pah, vh);
                }
            }
            __syncthreads();
        }
        int r0 = wm * 16 + gr;
#pragma unroll
        for (int jn = 0; jn < 2; jn++) {
            int col0 = wn * 16 + jn * 8 + 2 * t4;
#pragma unroll
            for (int qq = 0; qq < 2; qq++) {
                int row = r0 + qq * 8;
                float z0 = zc[jn][qq * 2 + 0], z1 = zc[jn][qq * 2 + 1];
#pragma unroll
                for (int d = 0; d < cND; d++) {
                    float hv = QES[row * 16 + d];
                    z0 += hv * VSUM[d * 32 + col0];
                    z1 += hv * VSUM[d * 32 + col0 + 1];
                }
                float ri = RINV[row];
                *(float2*)&g_z[(size_t)(b * cL + l0 + row) * cD + h * 32 + col0] =
                    make_float2(z0 * ri, z1 * ri);
            }
        }
    }
}

// ------------------------- layernorm of (X + R1 + R2) -----------------------
__global__ void ln3_kernel(const float* __restrict__ X, const float* __restrict__ R1,
                           const float* __restrict__ R2,
                           const float* __restrict__ gg, const float* __restrict__ bb,
                           float* __restrict__ out) {
    int row = blockIdx.x, t = threadIdx.x;
    float lv[4];
    float s = 0.f;
#pragma unroll
    for (int r = 0; r < 4; r++) {
        int c = t + 128 * r;
        lv[r] = X[(size_t)row * cD + c] + R1[(size_t)row * cD + c] + R2[(size_t)row * cD + c];
        s += lv[r];
    }
    __shared__ float red[128];
    red[t] = s; __syncthreads();
#pragma unroll
    for (int st = 64; st > 0; st >>= 1) { if (t < st) red[t] += red[t + st]; __syncthreads(); }
    float mu = red[0] * (1.0f / cD);
    __syncthreads();
    float vs = 0.f;
#pragma unroll
    for (int r = 0; r < 4; r++) { float d = lv[r] - mu; vs += d * d; }
    red[t] = vs; __syncthreads();
#pragma unroll
    for (int st = 64; st > 0; st >>= 1) { if (t < st) red[t] += red[t + st]; __syncthreads(); }
    float inv = rsqrtf(red[0] * (1.0f / cD) + 1e-5f);
#pragma unroll
    for (int r = 0; r < 4; r++) {
        int c = t + 128 * r;
        out[(size_t)row * cD + c] = (lv[r] - mu) * inv * gg[c] + bb[c];
    }
}

// ------------------------- head ---------------------------------------------
__global__ void head_kernel(const float* __restrict__ Wm1, const float* __restrict__ bm1,
                            const float* __restrict__ Wm2, const float* __restrict__ bm2,
                            float* __restrict__ out) {
    int b = blockIdx.x, t = threadIdx.x;
    __shared__ float pooled[cD];
    float s = 0.f;
    for (int l = 0; l < cL; l++) s += g_h[(size_t)(b * cL + l) * cD + t];
    pooled[t] = s;
    __syncthreads();
    float r = bm1[t];
    for (int d = 0; d < cD; d++) r += pooled[d] * Wm1[(size_t)d * cM + t];
    r = fmaxf(r, 0.f);
    __shared__ float red[512];
    red[t] = r * Wm2[t];
    __syncthreads();
#pragma unroll
    for (int st = 256; st > 0; st >>= 1) { if (t < st) red[t] += red[t + st]; __syncthreads(); }
    if (t == 0) out[b] = red[0] + bm2[0];
}

// ===========================================================================
extern "C" void kernel_launch(void* const* d_in, const int* in_sizes, int n_in,
                              void* d_out, int out_size) {
    const int*   cell_types = (const int*)  d_in[0];
    const float* distances  = (const float*)d_in[1];
    const float* cell_emb   = (const float*)d_in[2];
    const float* Kqk = (const float*)d_in[3];
    const float* Kqr = (const float*)d_in[4];
    const float* Kkr = (const float*)d_in[5];
    const float* Vqk = (const float*)d_in[6];
    const float* Vqr = (const float*)d_in[7];
    const float* Vkr = (const float*)d_in[8];

    int iWq = 9, ibq, iWk, ibk, iWv, ibv, iWo, ibo;
    if (in_sizes[10] == cNL * cD) {
        ibq = 10; iWk = 11; ibk = 12; iWv = 13; ibv = 14; iWo = 15; ibo = 16;
    } else {
        iWk = 10; iWv = 11; iWo = 12; ibq = 13; ibk = 14; ibv = 15; ibo = 16;
    }
    const float* Wq = (const float*)d_in[iWq];
    const float* bq = (const float*)d_in[ibq];
    const float* Wk = (const float*)d_in[iWk];
    const float* bk = (const float*)d_in[ibk];
    const float* Wv = (const float*)d_in[iWv];
    const float* bv = (const float*)d_in[ibv];
    const float* Wo = (const float*)d_in[iWo];
    const float* bo = (const float*)d_in[ibo];
    const float* W1  = (const float*)d_in[17];
    const float* b1  = (const float*)d_in[18];
    const float* W2  = (const float*)d_in[19];
    const float* b2  = (const float*)d_in[20];
    const float* g1  = (const float*)d_in[21];
    const float* be1 = (const float*)d_in[22];
    const float* g2  = (const float*)d_in[23];
    const float* be2 = (const float*)d_in[24];
    const float* Wm1 = (const float*)d_in[25];
    const float* bm1 = (const float*)d_in[26];
    const float* Wm2 = (const float*)d_in[27];
    const float* bm2 = (const float*)d_in[28];
    float* out = (float*)d_out;

    float *p_h, *p_q, *p_k, *p_v, *p_z, *p_o, *p_o2, *p_h2, *p_f, *p_zb;
    uint32_t* p_wp;
    cudaGetSymbolAddress((void**)&p_h,  g_h);
    cudaGetSymbolAddress((void**)&p_q,  g_q);
    cudaGetSymbolAddress((void**)&p_k,  g_k);
    cudaGetSymbolAddress((void**)&p_v,  g_v);
    cudaGetSymbolAddress((void**)&p_z,  g_z);
    cudaGetSymbolAddress((void**)&p_o,  g_o);
    cudaGetSymbolAddress((void**)&p_o2, g_o2);
    cudaGetSymbolAddress((void**)&p_h2, g_h2);
    cudaGetSymbolAddress((void**)&p_f,  g_f);
    cudaGetSymbolAddress((void**)&p_zb, g_zb);
    cudaGetSymbolAddress((void**)&p_wp, g_wp);

    static const int FLASH_SMEM =
        (64 * SC_STRIDE) * 4 + 64 * 512 +
        (2112 + 2 * KV_BUF + 1024 + 896 + 3584 + 128 + 256 + 64 + 448 + 16) * 4;
    cudaFuncSetAttribute(flash_attn_kernel,
                         cudaFuncAttributeMaxDynamicSharedMemorySize, FLASH_SMEM);

    const int SM128 = 3 * (A_FLOATS + 32 * 136) * 4;
    const int SM64  = 3 * (A_FLOATS + 32 * 72) * 4;
    cudaFuncSetAttribute(mma_gemm<128, false, true>,
                         cudaFuncAttributeMaxDynamicSharedMemorySize, SM128);
    cudaFuncSetAttribute(mma_gemm<128, true, false>,
                         cudaFuncAttributeMaxDynamicSharedMemorySize, SM128);
    cudaFuncSetAttribute(mma_gemm<64, false, true>,
                         cudaFuncAttributeMaxDynamicSharedMemorySize, SM64);

    didx_kernel<<<(cB * cL * cL) / 256, 256>>>(distances);
    embed_kernel<<<cBL, 256>>>(cell_types, cell_emb);
    prep_kernel<<<1, 448>>>(Kkr, Vqk, Vqr, Vkr);

    dim3 wt(256);
    wconv_kernel<<<dim3(16, 32, 8), wt>>>(Wq, p_wp + 0,       cD, cD, (size_t)cD * cD, WPL);
    wconv_kernel<<<dim3(16, 32, 8), wt>>>(Wk, p_wp + 262144,  cD, cD, (size_t)cD * cD, WPL);
    wconv_kernel<<<dim3(16, 32, 8), wt>>>(Wv, p_wp + 524288,  cD, cD, (size_t)cD * cD, WPL);
    wconv_kernel<<<dim3(16, 32, 8), wt>>>(Wo, p_wp + 786432,  cD, cD, (size_t)cD * cD, WPL);
    wconv_kernel<<<dim3(64, 32, 8), wt>>>(W1, p_wp + 1048576, cD, cFF, (size_t)cD * cFF, WPL);
    wconv_kernel<<<dim3(16, 128, 8), wt>>>(W2, p_wp + 2097152, cFF, cD, (size_t)cFF * cD, WPL);

    dim3 gQKV(cD / 128, cBL / 128, 3);      // 192 CTAs
    dim3 gSK (cD / 64, cBL / 128, 2);       // 256 CTAs (split-K O-proj / FF2)
    dim3 gFF1(cFF / 128, cBL / 128);        // 256 CTAs
    dim3 gFlash(cL / 64, cB * cH);          // 512 CTAs

    for (int ly = 0; ly < cNL; ly++) {
        const uint32_t* wp = p_wp + (size_t)ly * WPL;
        const float* bqp = bq + (size_t)ly * cD;
        const float* bkp = bk + (size_t)ly * cD;
        const float* bvp = bv + (size_t)ly * cD;
        const float* bop = bo + (size_t)ly * cD;
        const float* b1p = b1 + (size_t)ly * cFF;
        const float* b2p = b2 + (size_t)ly * cD;
        const float* g1p  = g1  + (size_t)ly * cD;
        const float* be1p = be1 + (size_t)ly * cD;
        const float* g2p  = g2  + (size_t)ly * cD;
        const float* be2p = be2 + (size_t)ly * cD;

        GArgs aQKV = { p_h, wp + 0, wp + 262144, wp + 524288,
                       bqp, bkp, bvp, p_q, p_k, p_v };
        mma_gemm<128, false, true><<<gQKV, 256, SM128>>>(aQKV, cBL, cD, cD, cD, 0, 131072);

        qke_kernel<<<cBL, 256>>>(Kqk, Kqr);
        flash_attn_kernel<<<gFlash, 256, FLASH_SMEM>>>();

        GArgs aO = { p_z, wp + 786432, wp + 786432 + 65536, wp + 786432 + 65536,
                     bop, p_zb, p_zb, p_o, p_o2, p_o2 };
        mma_gemm<64, false, true><<<gSK, 256, SM64>>>(aO, cBL, cD, 256, cD, 256, 131072);
        ln3_kernel<<<cBL, 128>>>(p_h, p_o, p_o2, g1p, be1p, p_h2);

        GArgs aF1 = { p_h2, wp + 1048576, 0, 0, b1p, 0, 0, p_f, 0, 0 };
        mma_gemm<128, true, false><<<gFF1, 256, SM128>>>(aF1, cBL, cFF, cD, cD, 0, 524288);

        GArgs aF2 = { p_f, wp + 2097152, wp + 2097152 + 262144, wp + 2097152 + 262144,
                      b2p, p_zb, p_zb, p_o, p_o2, p_o2 };
        mma_gemm<64, false, true><<<gSK, 256, SM64>>>(aF2, cBL, cD, 1024, cFF, 1024, 524288);
        ln3_kernel<<<cBL, 128>>>(p_h2, p_o, p_o2, g2p, be2p, p_h);
    }

    head_kernel<<<cB, 512>>>(Wm1, bm1, Wm2, bm2, out);
}

// round 17
// speedup vs baseline: 1.2730x; 1.0296x over previous
#include <cuda_runtime.h>
#include <math.h>
#include <stdint.h>

#define cB 4
#define cL 512
#define cD 512
#define cH 16
#define cKH 32
#define cFF 2048
#define cNL 8
#define cND 14
#define cM 512
#define cBL (cB*cL)
#define SCALEF 0.17677669529663687f  // 1/sqrt(32)

// ------------------------- scratch (static device globals) ------------------
__device__ float g_h [cBL*cD];
__device__ float g_q [cBL*cD];
__device__ float g_k [cBL*cD];
__device__ float g_v [cBL*cD];
__device__ float g_z [cBL*cD];
__device__ float g_o [cBL*cD];
__device__ float g_o2[cBL*cD];
__device__ float g_h2[cBL*cD];
__device__ float g_f [cBL*cFF];
__device__ unsigned char g_didx[cB*cL*cL];
__device__ float g_Vsum[cND*cKH];
__device__ float g_sumKkr[cND];
__device__ float g_zb[cD];          // zero bias (never written)

#define WPL 3145728
__device__ uint32_t g_wp[(size_t)cNL * WPL];

// ------------------------- helpers ------------------------------------------
__device__ __forceinline__ uint32_t smem_u32(const void* p) {
    uint32_t a;
    asm("{ .reg .u64 t; cvta.to.shared.u64 t, %1; cvt.u32.u64 %0, t; }" : "=r"(a) : "l"(p));
    return a;
}
__device__ __forceinline__ void cpasync16(uint32_t dst, const void* src) {
    asm volatile("cp.async.cg.shared.global [%0], [%1], 16;" :: "r"(dst), "l"(src));
}
#define CP_COMMIT() asm volatile("cp.async.commit_group;" ::: "memory")
#define CP_WAIT1()  asm volatile("cp.async.wait_group 1;" ::: "memory")
#define CP_WAIT0()  asm volatile("cp.async.wait_group 0;" ::: "memory")

// split (x0,x1) into packed bf16x2 hi + lo, low half = x0
__device__ __forceinline__ void split2(float x0, float x1, uint32_t& hi, uint32_t& lo) {
    uint32_t h;
    asm("cvt.rn.bf16x2.f32 %0, %1, %2;" : "=r"(h) : "f"(x1), "f"(x0));
    float h0 = __uint_as_float(h << 16);
    float h1 = __uint_as_float(h & 0xffff0000u);
    uint32_t l;
    asm("cvt.rn.bf16x2.f32 %0, %1, %2;" : "=r"(l) : "f"(x1 - h1), "f"(x0 - h0));
    hi = h; lo = l;
}
__device__ __forceinline__ void mma_bf16(float* c, const uint32_t* a, const uint32_t* b) {
    asm volatile(
        "mma.sync.aligned.m16n8k16.row.col.f32.bf16.bf16.f32 "
        "{%0,%1,%2,%3}, {%4,%5,%6,%7}, {%8,%9}, {%0,%1,%2,%3};\n"
        : "+f"(c[0]), "+f"(c[1]), "+f"(c[2]), "+f"(c[3])
        : "r"(a[0]), "r"(a[1]), "r"(a[2]), "r"(a[3]), "r"(b[0]), "r"(b[1]));
}

// ------------------------- weight conversion pre-pass ------------------------
__global__ void wconv_kernel(const float* __restrict__ src, uint32_t* __restrict__ dst,
                             int K, int N, size_t sStride, size_t dStride) {
    int ly = blockIdx.z;
    const float* s = src + (size_t)ly * sStride;
    uint32_t* d = dst + (size_t)ly * dStride;
    int t = threadIdx.x;
    int n  = blockIdx.x * 32 + (t & 31);
    int k2 = blockIdx.y * 8 + (t >> 5);
    float w0 = s[(size_t)(2 * k2) * N + n];
    float w1 = s[(size_t)(2 * k2 + 1) * N + n];
    uint32_t hi, lo;
    split2(w0, w1, hi, lo);
    size_t loSz = (size_t)(K / 2) * N;
    d[(size_t)k2 * N + n] = hi;
    d[loSz + (size_t)k2 * N + n] = lo;
}

// ------------------------- bf16 3-term tensor-core GEMM (BK=32) --------------
struct GArgs {
    const float* A;
    const uint32_t* W0; const uint32_t* W1; const uint32_t* W2;
    const float* c0; const float* c1; const float* c2;
    float* C0; float* C1; float* C2;
};

#define A_STRIDE 36
#define A_FLOATS (128 * A_STRIDE)

template<int BN, bool GELU, bool TRIPLE>
__global__ __launch_bounds__(256, 2) void mma_gemm(GArgs args, int Md, int Nd, int Kd,
                                                   int ldA, int aStep, int loOff) {
    constexpr int BSTR = BN + 8;
    constexpr int STAGE = A_FLOATS + 32 * BSTR;
    constexpr int NT = BN / 16;
    constexpr int BCH = 16 * BN / 4;
    extern __shared__ float smem[];
    uint32_t smb = smem_u32(smem);

    int t = threadIdx.x;
    const float* A = args.A;
    const uint32_t* W; const float* bias; float* C;
    if (TRIPLE) {
        int z = blockIdx.z;
        A   += (size_t)z * aStep;
        W    = (z == 0) ? args.W0 : (z == 1) ? args.W1 : args.W2;
        bias = (z == 0) ? args.c0 : (z == 1) ? args.c1 : args.c2;
        C    = (z == 0) ? args.C0 : (z == 1) ? args.C1 : args.C2;
    } else { W = args.W0; bias = args.c0; C = args.C0; }

    int m0 = blockIdx.y * 128, n0 = blockIdx.x * BN;

    auto issue = [&](int ch, int s) {
        int k0  = ch << 5;
        int k2b = ch << 4;
        uint32_t sa = smb + (uint32_t)(s * STAGE) * 4;
        uint32_t sb = sa + A_FLOATS * 4;
#pragma unroll
        for (int it = 0; it < 4; it++) {
            int idx = t + it * 256;
            int row = idx >> 3, c4 = (idx & 7) << 2;
            cpasync16(sa + (uint32_t)(row * A_STRIDE + c4) * 4,
                      &A[(size_t)(m0 + row) * ldA + k0 + c4]);
        }
#pragma unroll
        for (int it = 0; it < (2 * BCH) / 256; it++) {
            int idx = t + it * 256;
            int arr = (idx >= BCH) ? 1 : 0;
            int ci  = idx - arr * BCH;
            int row = ci / (BN / 4), c4 = (ci % (BN / 4)) << 2;
            cpasync16(sb + (uint32_t)((arr * 16 + row) * BSTR + c4) * 4,
                      &W[(size_t)(arr ? loOff : 0) + (size_t)(k2b + row) * Nd + n0 + c4]);
        }
    };

    int lane = t & 31, wid = t >> 5;
    int wm = wid & 3, wn = wid >> 2;
    int gr = lane >> 2, t4 = lane & 3;

    float c[2][NT][4];
#pragma unroll
    for (int i = 0; i < 2; i++)
#pragma unroll
        for (int j = 0; j < NT; j++)
#pragma unroll
            for (int q = 0; q < 4; q++) c[i][j][q] = 0.f;

    int nc = Kd >> 5;
    issue(0, 0); CP_COMMIT();
    issue(1, 1); CP_COMMIT();

    for (int ch = 0; ch < nc; ch++) {
        CP_WAIT1();
        __syncthreads();
        if (ch + 2 < nc) issue(ch + 2, (ch + 2) % 3);
        CP_COMMIT();

        const float* sA = smem + (ch % 3) * STAGE;
        const uint32_t* sBhi = (const uint32_t*)(sA + A_FLOATS);
        const uint32_t* sBlo = sBhi + 16 * BSTR;

#pragma unroll
        for (int ks = 0; ks < 2; ks++) {
            int kc = ks * 16 + 2 * t4;
            uint32_t ah[2][4], al[2][4];
#pragma unroll
            for (int i = 0; i < 2; i++) {
                int r0 = wm * 32 + i * 16 + gr;
                float2 p00 = *(const float2*)&sA[r0 * A_STRIDE + kc];
                float2 p10 = *(const float2*)&sA[(r0 + 8) * A_STRIDE + kc];
                float2 p01 = *(const float2*)&sA[r0 * A_STRIDE + kc + 8];
                float2 p11 = *(const float2*)&sA[(r0 + 8) * A_STRIDE + kc + 8];
                split2(p00.x, p00.y, ah[i][0], al[i][0]);
                split2(p10.x, p10.y, ah[i][1], al[i][1]);
                split2(p01.x, p01.y, ah[i][2], al[i][2]);
                split2(p11.x, p11.y, ah[i][3], al[i][3]);
            }
#pragma unroll
            for (int j = 0; j < NT; j++) {
                int n = wn * (BN / 2) + j * 8 + gr;
                uint32_t bh[2], bl[2];
                bh[0] = sBhi[(ks * 8 + t4) * BSTR + n];
                bh[1] = sBhi[(ks * 8 + t4 + 4) * BSTR + n];
                bl[0] = sBlo[(ks * 8 + t4) * BSTR + n];
                bl[1] = sBlo[(ks * 8 + t4 + 4) * BSTR + n];
#pragma unroll
                for (int i = 0; i < 2; i++) {
                    mma_bf16(c[i][j], al[i], bh);
                    mma_bf16(c[i][j], ah[i], bl);
                    mma_bf16(c[i][j], ah[i], bh);
                }
            }
        }
    }

#pragma unroll
    for (int i = 0; i < 2; i++) {
        int rb = m0 + wm * 32 + i * 16 + gr;
#pragma unroll
        for (int j = 0; j < NT; j++) {
            int col = n0 + wn * (BN / 2) + j * 8 + t4 * 2;
            float2 bb = *(const float2*)&bias[col];
            float v0 = c[i][j][0] + bb.x, v1 = c[i][j][1] + bb.y;
            float v2 = c[i][j][2] + bb.x, v3 = c[i][j][3] + bb.y;
            if (GELU) {
                v0 = 0.5f * v0 * (1.0f + erff(v0 * 0.70710678118654752f));
                v1 = 0.5f * v1 * (1.0f + erff(v1 * 0.70710678118654752f));
                v2 = 0.5f * v2 * (1.0f + erff(v2 * 0.70710678118654752f));
                v3 = 0.5f * v3 * (1.0f + erff(v3 * 0.70710678118654752f));
            }
            *(float2*)&C[(size_t)rb * Nd + col] = make_float2(v0, v1);
            *(float2*)&C[(size_t)(rb + 8) * Nd + col] = make_float2(v2, v3);
        }
    }
}

// ------------------------- distance bucketize -------------------------------
__global__ void didx_kernel(const float* __restrict__ dist) {
    int i = blockIdx.x * blockDim.x + threadIdx.x;
    float d = dist[i];
    int idx = 0;
#pragma unroll
    for (int j = 1; j <= 14; j++) idx += (10.0f * (float)j < d) ? 1 : 0;
    if (idx > 13) idx = 13;
    g_didx[i] = (unsigned char)idx;
}

// ------------------------- embedding gather ---------------------------------
__global__ void embed_kernel(const int* __restrict__ ct, const float* __restrict__ emb) {
    int row = blockIdx.x;
    int c0  = ct[row];
    for (int c = threadIdx.x; c < cD; c += blockDim.x)
        g_h[(size_t)row * cD + c] = emb[(size_t)c0 * cD + c];
}

// ------------------------- tiny precompute ----------------------------------
__global__ void prep_kernel(const float* __restrict__ Kkr,
                            const float* __restrict__ Vqk,
                            const float* __restrict__ Vqr,
                            const float* __restrict__ Vkr) {
    int t = threadIdx.x;
    if (t < cND * cKH) g_Vsum[t] = Vqk[t] + Vqr[t] + Vkr[t];
    if (t < cND) {
        float s = 0.f;
        for (int k = 0; k < cKH; k++) s += Kkr[t * cKH + k];
        g_sumKkr[t] = s;
    }
}

// ------------------------- fused flash attention ----------------------------
// bf16 3-term MMA; cp.async double-buffered K/V; in-kernel qE/kE; vec softmax.
#define SC_STRIDE 520
#define KV_STR 36
#define KV_BUF (64 * KV_STR)
__global__ __launch_bounds__(256) void flash_attn_kernel(const float* __restrict__ Kqk,
                                                         const float* __restrict__ Kqr) {
    extern __shared__ char smraw[];
    float* SC            = (float*)smraw;                         // 64*520
    unsigned char* DIDX  = (unsigned char*)(SC + 64 * SC_STRIDE); // 64*512 B
    float* QS   = (float*)(DIDX + 64 * 512);  // 2112
    float* KV   = QS + 2112;                  // 2 x 2304
    float* QES  = KV + 2 * KV_BUF;            // 1024 (qE, then attn-hist)
    float* KES  = QES + 1024;                 // 896 packed [64][14]
    float* HIST = KES + 896;                  // 3584
    float* RMAX = HIST + 3584;                // 128
    float* REDS = RMAX + 128;                 // 256
    float* RINV = REDS + 256;                 // 64
    float* VSUM = RINV + 64;                  // 448
    float* SKR  = VSUM + 448;                 // 16
    float* KQK  = SKR + 16;                   // 14*33 = 462
    float* KQR  = KQK + 462;                  // 462
    uint32_t kvB = smem_u32(KV);

    int bh = blockIdx.y;
    int b  = bh >> 4, h = bh & 15;
    int l0 = blockIdx.x * 64;
    int t  = threadIdx.x;
    int lane = t & 31, wid = t >> 5;
    int wm = wid & 3, wn = wid >> 2;
    int gr = lane >> 2, t4 = lane & 3;

    auto issueK = [&](int xt, int bufi) {
        int x0 = xt * 64;
        uint32_t dst = kvB + (uint32_t)(bufi * KV_BUF) * 4;
#pragma unroll
        for (int it = 0; it < 2; it++) {
            int idx = t + it * 256;
            int row = idx >> 3, c4 = (idx & 7) << 2;
            cpasync16(dst + (uint32_t)(row * KV_STR + c4) * 4,
                      &g_k[(size_t)(b * cL + x0 + row) * cD + h * 32 + c4]);
        }
    };
    auto issueV = [&](int xt, int bufi) {
        int x0 = xt * 64;
        uint32_t dst = kvB + (uint32_t)(bufi * KV_BUF) * 4;
#pragma unroll
        for (int it = 0; it < 2; it++) {
            int idx = t + it * 256;
            int row = idx >> 3, c4 = (idx & 7) << 2;
            cpasync16(dst + (uint32_t)(row * KV_STR + c4) * 4,
                      &g_v[(size_t)(b * cL + x0 + row) * cD + h * 32 + c4]);
        }
    };

    // ---- preload Q, didx strip, Vsum, sumKkr, Kqk/Kqr; prefetch K tile 0 ----
    issueK(0, 0); CP_COMMIT();
#pragma unroll
    for (int r = 0; r < 8; r++) {
        int l = r * 8 + (t >> 5), k = t & 31;
        QS[l * 33 + k] = g_q[(size_t)(b * cL + l0 + l) * cD + h * 32 + k];
    }
    {
        const int4* src = (const int4*)(g_didx + ((size_t)b * cL + l0) * cL);
        for (int idx = t; idx < 2048; idx += 256) ((int4*)DIDX)[idx] = src[idx];
    }
    for (int idx = t; idx < cND * 32; idx += 256) VSUM[idx] = g_Vsum[idx];
    if (t < cND) SKR[t] = g_sumKkr[t];
    for (int idx = t; idx < cND * 32; idx += 256) {
        int d = idx >> 5, k = idx & 31;
        KQK[d * 33 + k] = Kqk[idx];
        KQR[d * 33 + k] = Kqr[idx];
    }
    __syncthreads();

    // ---- qE: QES[l*16+d] = sum_k QS[l][k] * Kqk[d][k] ----
    for (int idx = t; idx < 64 * cND; idx += 256) {
        int l = idx / cND, d = idx - l * cND;
        float s = 0.f;
#pragma unroll
        for (int k = 0; k < 32; k++) s += QS[l * 33 + k] * KQK[d * 33 + k];
        QES[l * 16 + d] = s;
    }

    // ---- Q fragments (hoisted) ----
    uint32_t qh[2][4], ql[2][4];
    {
        int r0 = wm * 16 + gr;
#pragma unroll
        for (int ks = 0; ks < 2; ks++) {
            int k0 = ks * 16 + 2 * t4;
            split2(QS[r0 * 33 + k0],       QS[r0 * 33 + k0 + 1],       qh[ks][0], ql[ks][0]);
            split2(QS[(r0 + 8) * 33 + k0], QS[(r0 + 8) * 33 + k0 + 1], qh[ks][1], ql[ks][1]);
            split2(QS[r0 * 33 + k0 + 8],   QS[r0 * 33 + k0 + 9],       qh[ks][2], ql[ks][2]);
            split2(QS[(r0 + 8) * 33 + k0 + 8], QS[(r0 + 8) * 33 + k0 + 9], qh[ks][3], ql[ks][3]);
        }
    }
    float mx0 = -1e30f, mx1 = -1e30f;

    // ---- phase 1: scores, double-buffered K; kE computed per tile ----
    for (int xt = 0; xt < 8; xt++) {
        int x0 = xt * 64;
        if (xt + 1 < 8) { issueK(xt + 1, (xt + 1) & 1); CP_COMMIT(); CP_WAIT1(); }
        else            { CP_WAIT0(); }
        __syncthreads();        // KS_ ready; prior-tile KES reads complete
        const float* KS_ = KV + (xt & 1) * KV_BUF;

        // kE for this tile: KES[ct*14+d] = sum_k KS_[ct][k] * Kqr[d][k]
        for (int idx = t; idx < 64 * cND; idx += 256) {
            int ct = idx / cND, d = idx - ct * cND;
            float s = 0.f;
#pragma unroll
            for (int k = 0; k < 32; k++) s += KS_[ct * KV_STR + k] * KQR[d * 33 + k];
            KES[idx] = s;
        }

        float acc[4][4] = {};
#pragma unroll
        for (int jn = 0; jn < 4; jn++) {
            int c0 = wn * 32 + jn * 8 + gr;
#pragma unroll
            for (int ks = 0; ks < 2; ks++) {
                int k0 = ks * 16 + 2 * t4;
                uint32_t kb[2], kl[2];
                split2(KS_[c0 * KV_STR + k0],     KS_[c0 * KV_STR + k0 + 1], kb[0], kl[0]);
                split2(KS_[c0 * KV_STR + k0 + 8], KS_[c0 * KV_STR + k0 + 9], kb[1], kl[1]);
                mma_bf16(acc[jn], ql[ks], kb);
                mma_bf16(acc[jn], qh[ks], kl);
                mma_bf16(acc[jn], qh[ks], kb);
            }
        }
        __syncthreads();        // KES writes visible before epilogue reads
        int r0 = wm * 16 + gr;
#pragma unroll
        for (int jn = 0; jn < 4; jn++) {
            int cbase = wn * 32 + jn * 8 + 2 * t4;
#pragma unroll
            for (int q = 0; q < 4; q++) {
                int row = (q & 2) ? r0 + 8 : r0;
                int ct  = cbase + (q & 1);
                int col = x0 + ct;
                int d = DIDX[row * 512 + col];
                float e = (acc[jn][q] + QES[row * 16 + d] + KES[ct * cND + d] + SKR[d]) * SCALEF;
                SC[row * SC_STRIDE + col] = e;
                if (q & 2) mx1 = fmaxf(mx1, e); else mx0 = fmaxf(mx0, e);
            }
        }
    }
    mx0 = fmaxf(mx0, __shfl_xor_sync(0xffffffffu, mx0, 1));
    mx0 = fmaxf(mx0, __shfl_xor_sync(0xffffffffu, mx0, 2));
    mx1 = fmaxf(mx1, __shfl_xor_sync(0xffffffffu, mx1, 1));
    mx1 = fmaxf(mx1, __shfl_xor_sync(0xffffffffu, mx1, 2));
    if (t4 == 0) {
        RMAX[(wm * 16 + gr) + 64 * wn]     = mx0;
        RMAX[(wm * 16 + gr + 8) + 64 * wn] = mx1;
    }
    // prefetch V tile 0 (overlaps entire softmax pass)
    issueV(0, 0); CP_COMMIT();
    __syncthreads();

    // ---- phase 2: exp + row-sum + bucket histogram (vectorized) ----
    {
        int r = t >> 2, j = t & 3;
        float m = fmaxf(RMAX[r], RMAX[r + 64]);
#pragma unroll
        for (int d = 0; d < cND; d++) HIST[d * 256 + t] = 0.f;
        float s = 0.f;
        float4* scrow = (float4*)&SC[r * SC_STRIDE + j * 128];
        const uchar4* drow = (const uchar4*)&DIDX[r * 512 + j * 128];
        for (int i = 0; i < 32; i++) {
            float4 p = scrow[i];
            uchar4 d4 = drow[i];
            p.x = __expf(p.x - m); p.y = __expf(p.y - m);
            p.z = __expf(p.z - m); p.w = __expf(p.w - m);
            s += (p.x + p.y) + (p.z + p.w);
            HIST[d4.x * 256 + t] += p.x;
            HIST[d4.y * 256 + t] += p.y;
            HIST[d4.z * 256 + t] += p.z;
            HIST[d4.w * 256 + t] += p.w;
            scrow[i] = p;
        }
        REDS[t] = s;
        __syncthreads();
        if (t < 64) RINV[t] = 1.0f / (REDS[4 * t] + REDS[4 * t + 1] + REDS[4 * t + 2] + REDS[4 * t + 3]);
        for (int idx = t; idx < 64 * cND; idx += 256) {
            int d = idx >> 6, r2 = idx & 63;
            QES[r2 * 16 + d] = HIST[d * 256 + 4 * r2]     + HIST[d * 256 + 4 * r2 + 1]
                             + HIST[d * 256 + 4 * r2 + 2] + HIST[d * 256 + 4 * r2 + 3];
        }
        __syncthreads();
    }

    // ---- phase 3: z = P@V (MMA) + hist@Vsum, normalized; double-buffered V --
    {
        float zc[2][4] = {};
        for (int xt = 0; xt < 8; xt++) {
            if (xt + 1 < 8) { issueV(xt + 1, (xt + 1) & 1); CP_COMMIT(); CP_WAIT1(); }
            else            { CP_WAIT0(); }
            __syncthreads();
            const float* VS_ = KV + (xt & 1) * KV_BUF;
            int x0 = xt * 64;
            int r0 = wm * 16 + gr;
#pragma unroll
            for (int ks = 0; ks < 4; ks++) {
                int kk = x0 + ks * 16 + 2 * t4;
                uint32_t pah[4], pal[4];
                split2(SC[r0 * SC_STRIDE + kk],           SC[r0 * SC_STRIDE + kk + 1],           pah[0], pal[0]);
                split2(SC[(r0 + 8) * SC_STRIDE + kk],     SC[(r0 + 8) * SC_STRIDE + kk + 1],     pah[1], pal[1]);
                split2(SC[r0 * SC_STRIDE + kk + 8],       SC[r0 * SC_STRIDE + kk + 9],           pah[2], pal[2]);
                split2(SC[(r0 + 8) * SC_STRIDE + kk + 8], SC[(r0 + 8) * SC_STRIDE + kk + 9],     pah[3], pal[3]);
                int kv = ks * 16 + 2 * t4;
#pragma unroll
                for (int jn = 0; jn < 2; jn++) {
                    int col = wn * 16 + jn * 8 + gr;
                    uint32_t vh[2], vl[2];
                    split2(VS_[kv * KV_STR + col],       VS_[(kv + 1) * KV_STR + col], vh[0], vl[0]);
                    split2(VS_[(kv + 8) * KV_STR + col], VS_[(kv + 9) * KV_STR + col], vh[1], vl[1]);
                    mma_bf16(zc[jn], pal, vh);
                    mma_bf16(zc[jn], pah, vl);
                    mma_bf16(zc[jn], pah, vh);
                }
            }
            __syncthreads();
        }
        int r0 = wm * 16 + gr;
#pragma unroll
        for (int jn = 0; jn < 2; jn++) {
            int col0 = wn * 16 + jn * 8 + 2 * t4;
#pragma unroll
            for (int qq = 0; qq < 2; qq++) {
                int row = r0 + qq * 8;
                float z0 = zc[jn][qq * 2 + 0], z1 = zc[jn][qq * 2 + 1];
#pragma unroll
                for (int d = 0; d < cND; d++) {
                    float hv = QES[row * 16 + d];
                    z0 += hv * VSUM[d * 32 + col0];
                    z1 += hv * VSUM[d * 32 + col0 + 1];
                }
                float ri = RINV[row];
                *(float2*)&g_z[(size_t)(b * cL + l0 + row) * cD + h * 32 + col0] =
                    make_float2(z0 * ri, z1 * ri);
            }
        }
    }
}

// ------------------------- layernorm of (X + R1 + R2) -----------------------
__global__ void ln3_kernel(const float* __restrict__ X, const float* __restrict__ R1,
                           const float* __restrict__ R2,
                           const float* __restrict__ gg, const float* __restrict__ bb,
                           float* __restrict__ out) {
    int row = blockIdx.x, t = threadIdx.x;
    float lv[4];
    float s = 0.f;
#pragma unroll
    for (int r = 0; r < 4; r++) {
        int c = t + 128 * r;
        lv[r] = X[(size_t)row * cD + c] + R1[(size_t)row * cD + c] + R2[(size_t)row * cD + c];
        s += lv[r];
    }
    __shared__ float red[128];
    red[t] = s; __syncthreads();
#pragma unroll
    for (int st = 64; st > 0; st >>= 1) { if (t < st) red[t] += red[t + st]; __syncthreads(); }
    float mu = red[0] * (1.0f / cD);
    __syncthreads();
    float vs = 0.f;
#pragma unroll
    for (int r = 0; r < 4; r++) { float d = lv[r] - mu; vs += d * d; }
    red[t] = vs; __syncthreads();
#pragma unroll
    for (int st = 64; st > 0; st >>= 1) { if (t < st) red[t] += red[t + st]; __syncthreads(); }
    float inv = rsqrtf(red[0] * (1.0f / cD) + 1e-5f);
#pragma unroll
    for (int r = 0; r < 4; r++) {
        int c = t + 128 * r;
        out[(size_t)row * cD + c] = (lv[r] - mu) * inv * gg[c] + bb[c];
    }
}

// ------------------------- head ---------------------------------------------
__global__ void head_kernel(const float* __restrict__ Wm1, const float* __restrict__ bm1,
                            const float* __restrict__ Wm2, const float* __restrict__ bm2,
                            float* __restrict__ out) {
    int b = blockIdx.x, t = threadIdx.x;
    __shared__ float pooled[cD];
    float s = 0.f;
    for (int l = 0; l < cL; l++) s += g_h[(size_t)(b * cL + l) * cD + t];
    pooled[t] = s;
    __syncthreads();
    float r = bm1[t];
    for (int d = 0; d < cD; d++) r += pooled[d] * Wm1[(size_t)d * cM + t];
    r = fmaxf(r, 0.f);
    __shared__ float red[512];
    red[t] = r * Wm2[t];
    __syncthreads();
#pragma unroll
    for (int st = 256; st > 0; st >>= 1) { if (t < st) red[t] += red[t + st]; __syncthreads(); }
    if (t == 0) out[b] = red[0] + bm2[0];
}

// ===========================================================================
extern "C" void kernel_launch(void* const* d_in, const int* in_sizes, int n_in,
                              void* d_out, int out_size) {
    const int*   cell_types = (const int*)  d_in[0];
    const float* distances  = (const float*)d_in[1];
    const float* cell_emb   = (const float*)d_in[2];
    const float* Kqk = (const float*)d_in[3];
    const float* Kqr = (const float*)d_in[4];
    const float* Kkr = (const float*)d_in[5];
    const float* Vqk = (const float*)d_in[6];
    const float* Vqr = (const float*)d_in[7];
    const float* Vkr = (const float*)d_in[8];

    int iWq = 9, ibq, iWk, ibk, iWv, ibv, iWo, ibo;
    if (in_sizes[10] == cNL * cD) {
        ibq = 10; iWk = 11; ibk = 12; iWv = 13; ibv = 14; iWo = 15; ibo = 16;
    } else {
        iWk = 10; iWv = 11; iWo = 12; ibq = 13; ibk = 14; ibv = 15; ibo = 16;
    }
    const float* Wq = (const float*)d_in[iWq];
    const float* bq = (const float*)d_in[ibq];
    const float* Wk = (const float*)d_in[iWk];
    const float* bk = (const float*)d_in[ibk];
    const float* Wv = (const float*)d_in[iWv];
    const float* bv = (const float*)d_in[ibv];
    const float* Wo = (const float*)d_in[iWo];
    const float* bo = (const float*)d_in[ibo];
    const float* W1  = (const float*)d_in[17];
    const float* b1  = (const float*)d_in[18];
    const float* W2  = (const float*)d_in[19];
    const float* b2  = (const float*)d_in[20];
    const float* g1  = (const float*)d_in[21];
    const float* be1 = (const float*)d_in[22];
    const float* g2  = (const float*)d_in[23];
    const float* be2 = (const float*)d_in[24];
    const float* Wm1 = (const float*)d_in[25];
    const float* bm1 = (const float*)d_in[26];
    const float* Wm2 = (const float*)d_in[27];
    const float* bm2 = (const float*)d_in[28];
    float* out = (float*)d_out;

    float *p_h, *p_q, *p_k, *p_v, *p_z, *p_o, *p_o2, *p_h2, *p_f, *p_zb;
    uint32_t* p_wp;
    cudaGetSymbolAddress((void**)&p_h,  g_h);
    cudaGetSymbolAddress((void**)&p_q,  g_q);
    cudaGetSymbolAddress((void**)&p_k,  g_k);
    cudaGetSymbolAddress((void**)&p_v,  g_v);
    cudaGetSymbolAddress((void**)&p_z,  g_z);
    cudaGetSymbolAddress((void**)&p_o,  g_o);
    cudaGetSymbolAddress((void**)&p_o2, g_o2);
    cudaGetSymbolAddress((void**)&p_h2, g_h2);
    cudaGetSymbolAddress((void**)&p_f,  g_f);
    cudaGetSymbolAddress((void**)&p_zb, g_zb);
    cudaGetSymbolAddress((void**)&p_wp, g_wp);

    static const int FLASH_SMEM =
        (64 * SC_STRIDE) * 4 + 64 * 512 +
        (2112 + 2 * KV_BUF + 1024 + 896 + 3584 + 128 + 256 + 64 + 448 + 16 + 462 + 462) * 4;
    cudaFuncSetAttribute(flash_attn_kernel,
                         cudaFuncAttributeMaxDynamicSharedMemorySize, FLASH_SMEM);

    const int SM128 = 3 * (A_FLOATS + 32 * 136) * 4;
    const int SM64  = 3 * (A_FLOATS + 32 * 72) * 4;
    cudaFuncSetAttribute(mma_gemm<128, false, true>,
                         cudaFuncAttributeMaxDynamicSharedMemorySize, SM128);
    cudaFuncSetAttribute(mma_gemm<128, true, false>,
                         cudaFuncAttributeMaxDynamicSharedMemorySize, SM128);
    cudaFuncSetAttribute(mma_gemm<64, false, true>,
                         cudaFuncAttributeMaxDynamicSharedMemorySize, SM64);

    didx_kernel<<<(cB * cL * cL) / 256, 256>>>(distances);
    embed_kernel<<<cBL, 256>>>(cell_types, cell_emb);
    prep_kernel<<<1, 448>>>(Kkr, Vqk, Vqr, Vkr);

    dim3 wt(256);
    wconv_kernel<<<dim3(16, 32, 8), wt>>>(Wq, p_wp + 0,       cD, cD, (size_t)cD * cD, WPL);
    wconv_kernel<<<dim3(16, 32, 8), wt>>>(Wk, p_wp + 262144,  cD, cD, (size_t)cD * cD, WPL);
    wconv_kernel<<<dim3(16, 32, 8), wt>>>(Wv, p_wp + 524288,  cD, cD, (size_t)cD * cD, WPL);
    wconv_kernel<<<dim3(16, 32, 8), wt>>>(Wo, p_wp + 786432,  cD, cD, (size_t)cD * cD, WPL);
    wconv_kernel<<<dim3(64, 32, 8), wt>>>(W1, p_wp + 1048576, cD, cFF, (size_t)cD * cFF, WPL);
    wconv_kernel<<<dim3(16, 128, 8), wt>>>(W2, p_wp + 2097152, cFF, cD, (size_t)cFF * cD, WPL);

    dim3 gQKV(cD / 128, cBL / 128, 3);      // 192 CTAs
    dim3 gSK (cD / 64, cBL / 128, 2);       // 256 CTAs (split-K O-proj / FF2)
    dim3 gFF1(cFF / 128, cBL / 128);        // 256 CTAs
    dim3 gFlash(cL / 64, cB * cH);          // 512 CTAs

    for (int ly = 0; ly < cNL; ly++) {
        const uint32_t* wp = p_wp + (size_t)ly * WPL;
        const float* bqp = bq + (size_t)ly * cD;
        const float* bkp = bk + (size_t)ly * cD;
        const float* bvp = bv + (size_t)ly * cD;
        const float* bop = bo + (size_t)ly * cD;
        const float* b1p = b1 + (size_t)ly * cFF;
        const float* b2p = b2 + (size_t)ly * cD;
        const float* g1p  = g1  + (size_t)ly * cD;
        const float* be1p = be1 + (size_t)ly * cD;
        const float* g2p  = g2  + (size_t)ly * cD;
        const float* be2p = be2 + (size_t)ly * cD;

        GArgs aQKV = { p_h, wp + 0, wp + 262144, wp + 524288,
                       bqp, bkp, bvp, p_q, p_k, p_v };
        mma_gemm<128, false, true><<<gQKV, 256, SM128>>>(aQKV, cBL, cD, cD, cD, 0, 131072);

        flash_attn_kernel<<<gFlash, 256, FLASH_SMEM>>>(Kqk, Kqr);

        GArgs aO = { p_z, wp + 786432, wp + 786432 + 65536, wp + 786432 + 65536,
                     bop, p_zb, p_zb, p_o, p_o2, p_o2 };
        mma_gemm<64, false, true><<<gSK, 256, SM64>>>(aO, cBL, cD, 256, cD, 256, 131072);
        ln3_kernel<<<cBL, 128>>>(p_h, p_o, p_o2, g1p, be1p, p_h2);

        GArgs aF1 = { p_h2, wp + 1048576, 0, 0, b1p, 0, 0, p_f, 0, 0 };
        mma_gemm<128, true, false><<<gFF1, 256, SM128>>>(aF1, cBL, cFF, cD, cD, 0, 524288);

        GArgs aF2 = { p_f, wp + 2097152, wp + 2097152 + 262144, wp + 2097152 + 262144,
                      b2p, p_zb, p_zb, p_o, p_o2, p_o2 };
        mma_gemm<64, false, true><<<gSK, 256, SM64>>>(aF2, cBL, cD, 1024, cFF, 1024, 524288);
        ln3_kernel<<<cBL, 128>>>(p_h2, p_o, p_o2, g2p, be2p, p_h);
    }

    head_kernel<<<cB, 512>>>(Wm1, bm1, Wm2, bm2, out);
}